// round 1
// baseline (speedup 1.0000x reference)
#include <cuda_runtime.h>
#include <math.h>

#define NN 100000
#define EE 1600000
#define DD 128

// ---------------- device scratch (no allocations allowed) ----------------
__device__ int   g_cnt[NN];        // in-degree (edges only)
__device__ int   g_rowptr[NN];     // CSR row starts (exclusive scan of cnt)
__device__ int   g_cursor[NN];     // fill cursors
__device__ float g_dinv[NN];       // rsqrt(deg+1)
__device__ int   g_csrc[EE];       // CSR source ids grouped by dst
__device__ int   g_srcb[EE];       // normalized src
__device__ int   g_dstb[EE];       // normalized dst
__device__ int   g_bsums[256];     // scan block sums
__device__ int   g_is64;           // edge dtype flag
__device__ float g_h[(size_t)NN * DD];   // GEMM output (pre-aggregation)
__device__ float g_f[(size_t)NN * DD];   // layer-1 activations

// ---------------- edge dtype detection + normalization ----------------
// If the edge buffer is int64 (little-endian, values < 2^31), every odd int32
// word is 0. If it is int32, odd words are random node ids (all-zero prob ~0).
__global__ void k_detect(const int* __restrict__ eb) {
    __shared__ int s_nz;
    if (threadIdx.x == 0) s_nz = 0;
    __syncthreads();
    int nz = 0;
    for (int i = threadIdx.x; i < 512; i += blockDim.x)
        nz += (eb[2 * i + 1] != 0);
    atomicAdd(&s_nz, nz);
    __syncthreads();
    if (threadIdx.x == 0) g_is64 = (s_nz == 0);
}

__global__ void k_extract(const int* __restrict__ eb, int e) {
    int i = blockIdx.x * blockDim.x + threadIdx.x;
    if (i >= e) return;
    if (g_is64) {
        g_srcb[i] = eb[2 * i];
        g_dstb[i] = eb[2 * (e + i)];
    } else {
        g_srcb[i] = eb[i];
        g_dstb[i] = eb[e + i];
    }
}

// ---------------- degree histogram + scan -> CSR ----------------
__global__ void k_zero(int n) {
    int i = blockIdx.x * blockDim.x + threadIdx.x;
    if (i < n) g_cnt[i] = 0;
}

__global__ void k_hist(int e) {
    int i = blockIdx.x * blockDim.x + threadIdx.x;
    if (i < e) atomicAdd(&g_cnt[g_dstb[i]], 1);
}

__global__ void k_scanA(int n) {
    __shared__ int sh[1024];
    int gi = blockIdx.x * 1024 + threadIdx.x;
    int v = (gi < n) ? g_cnt[gi] : 0;
    sh[threadIdx.x] = v;
    __syncthreads();
    for (int off = 1; off < 1024; off <<= 1) {
        int x = sh[threadIdx.x];
        int y = (threadIdx.x >= off) ? sh[threadIdx.x - off] : 0;
        __syncthreads();
        sh[threadIdx.x] = x + y;
        __syncthreads();
    }
    int incl = sh[threadIdx.x];
    if (gi < n) g_rowptr[gi] = incl - v;  // exclusive
    if (threadIdx.x == 1023) g_bsums[blockIdx.x] = incl;
}

__global__ void k_scanB(int nb) {
    if (threadIdx.x == 0 && blockIdx.x == 0) {
        int run = 0;
        for (int b = 0; b < nb; b++) {
            int t = g_bsums[b];
            g_bsums[b] = run;
            run += t;
        }
    }
}

__global__ void k_scanC(int n) {
    int i = blockIdx.x * blockDim.x + threadIdx.x;
    if (i >= n) return;
    int rp = g_rowptr[i] + g_bsums[i >> 10];
    g_rowptr[i] = rp;
    g_cursor[i] = rp;
    g_dinv[i] = rsqrtf((float)(g_cnt[i] + 1));  // +1 self loop
}

__global__ void k_fill(int e) {
    int i = blockIdx.x * blockDim.x + threadIdx.x;
    if (i >= e) return;
    int d = g_dstb[i];
    int p = atomicAdd(&g_cursor[d], 1);
    g_csrc[p] = g_srcb[i];
}

// ---------------- GEMM: C[n x 128] = A[n x 128] @ W[128 x 128] ----------------
// 128x128 block tile, 256 threads, 8x8 register tile. K=128 done in one pass.
__global__ void __launch_bounds__(256) k_gemm(const float* __restrict__ A,
                                              const float* __restrict__ W,
                                              float* __restrict__ C, int n) {
    extern __shared__ float sm[];
    float4* As4 = (float4*)sm;                  // 128 rows x 32 float4
    float4* Ws4 = (float4*)(sm + 128 * 128);    // 128 k    x 32 float4
    const int tid = threadIdx.x;
    const int row0 = blockIdx.x * 128;

    const float4* W4 = (const float4*)W;
    for (int i = tid; i < 4096; i += 256) Ws4[i] = W4[i];

    const float4* A4 = (const float4*)A;
    for (int i = tid; i < 4096; i += 256) {
        int r = i >> 5;
        float4 v = make_float4(0.f, 0.f, 0.f, 0.f);
        if (row0 + r < n) v = A4[(size_t)(row0 + r) * 32 + (i & 31)];
        As4[i] = v;
    }
    __syncthreads();

    const int tx = tid & 15;
    const int ty = tid >> 4;
    float acc[8][8];
#pragma unroll
    for (int i = 0; i < 8; i++)
#pragma unroll
        for (int j = 0; j < 8; j++) acc[i][j] = 0.f;

    for (int k4 = 0; k4 < 32; k4++) {
        float4 a[8];
#pragma unroll
        for (int i = 0; i < 8; i++) a[i] = As4[(ty * 8 + i) * 32 + k4];
#pragma unroll
        for (int kk = 0; kk < 4; kk++) {
            float4 wa = Ws4[(k4 * 4 + kk) * 32 + tx * 2];
            float4 wb = Ws4[(k4 * 4 + kk) * 32 + tx * 2 + 1];
#pragma unroll
            for (int i = 0; i < 8; i++) {
                float av = (kk == 0) ? a[i].x : (kk == 1) ? a[i].y
                         : (kk == 2) ? a[i].z : a[i].w;
                acc[i][0] += av * wa.x;
                acc[i][1] += av * wa.y;
                acc[i][2] += av * wa.z;
                acc[i][3] += av * wa.w;
                acc[i][4] += av * wb.x;
                acc[i][5] += av * wb.y;
                acc[i][6] += av * wb.z;
                acc[i][7] += av * wb.w;
            }
        }
    }

    float4* C4 = (float4*)C;
#pragma unroll
    for (int i = 0; i < 8; i++) {
        int r = row0 + ty * 8 + i;
        if (r < n) {
            C4[(size_t)r * 32 + tx * 2] =
                make_float4(acc[i][0], acc[i][1], acc[i][2], acc[i][3]);
            C4[(size_t)r * 32 + tx * 2 + 1] =
                make_float4(acc[i][4], acc[i][5], acc[i][6], acc[i][7]);
        }
    }
}

// ---------------- aggregation: out[i] = tanh(dinv[i]*(dinv[i]*h[i] + sum_j dinv[j]*h[j]) + b)
// Gather-only via CSR, one warp per node, zero float atomics.
__global__ void __launch_bounds__(256) k_agg(const float* __restrict__ H,
                                             const float* __restrict__ b,
                                             float* __restrict__ out, int n) {
    int wid = (blockIdx.x * blockDim.x + threadIdx.x) >> 5;
    int lane = threadIdx.x & 31;
    if (wid >= n) return;
    const float4* H4 = (const float4*)H;
    float di = g_dinv[wid];
    float4 hv = H4[(size_t)wid * 32 + lane];
    float ax = di * hv.x, ay = di * hv.y, az = di * hv.z, aw = di * hv.w;

    int beg = g_rowptr[wid];
    int cnt = g_cnt[wid];
    int j = 0;
    for (; j + 2 <= cnt; j += 2) {
        int s0 = g_csrc[beg + j];
        int s1 = g_csrc[beg + j + 1];
        float w0 = g_dinv[s0];
        float w1 = g_dinv[s1];
        float4 v0 = H4[(size_t)s0 * 32 + lane];
        float4 v1 = H4[(size_t)s1 * 32 + lane];
        ax += w0 * v0.x + w1 * v1.x;
        ay += w0 * v0.y + w1 * v1.y;
        az += w0 * v0.z + w1 * v1.z;
        aw += w0 * v0.w + w1 * v1.w;
    }
    if (j < cnt) {
        int s0 = g_csrc[beg + j];
        float w0 = g_dinv[s0];
        float4 v0 = H4[(size_t)s0 * 32 + lane];
        ax += w0 * v0.x;
        ay += w0 * v0.y;
        az += w0 * v0.z;
        aw += w0 * v0.w;
    }
    float4 bb = ((const float4*)b)[lane];
    float4 o;
    o.x = tanhf(di * ax + bb.x);
    o.y = tanhf(di * ay + bb.y);
    o.z = tanhf(di * az + bb.z);
    o.w = tanhf(di * aw + bb.w);
    ((float4*)out)[(size_t)wid * 32 + lane] = o;
}

// ---------------- FC head: out[i] = sigmoid(emb[i] . Wfc + bfc) ----------------
__global__ void __launch_bounds__(256) k_fc(const float* __restrict__ emb,
                                            const float* __restrict__ Wfc,
                                            const float* __restrict__ bfc,
                                            float* __restrict__ out, int n) {
    int wid = (blockIdx.x * blockDim.x + threadIdx.x) >> 5;
    int lane = threadIdx.x & 31;
    if (wid >= n) return;
    float4 e = ((const float4*)emb)[(size_t)wid * 32 + lane];
    float4 w = ((const float4*)Wfc)[lane];
    float s = e.x * w.x + e.y * w.y + e.z * w.z + e.w * w.w;
#pragma unroll
    for (int o = 16; o; o >>= 1) s += __shfl_xor_sync(0xFFFFFFFFu, s, o);
    if (lane == 0) out[wid] = 1.0f / (1.0f + expf(-(s + bfc[0])));
}

// ---------------- launch ----------------
extern "C" void kernel_launch(void* const* d_in, const int* in_sizes, int n_in,
                              void* d_out, int out_size) {
    const float* x   = (const float*)d_in[0];
    const int*   eb  = (const int*)d_in[1];
    const float* W1  = (const float*)d_in[2];
    const float* b1  = (const float*)d_in[3];
    const float* W2  = (const float*)d_in[4];
    const float* b2  = (const float*)d_in[5];
    const float* Wfc = (const float*)d_in[6];
    const float* bfc = (const float*)d_in[7];

    int n = in_sizes[0] / DD;   // 100000
    int e = in_sizes[1] / 2;    // 1600000 (element count is dtype-agnostic here)

    float* out = (float*)d_out;       // (out[N], embeddings[N*128]) concatenated
    float* emb = out + n;

    float *ph, *pf;
    cudaGetSymbolAddress((void**)&ph, g_h);
    cudaGetSymbolAddress((void**)&pf, g_f);

    const int T = 256;
    // --- graph preprocessing (shared by both conv layers) ---
    k_detect<<<1, 256>>>(eb);
    k_extract<<<(e + T - 1) / T, T>>>(eb, e);
    k_zero<<<(n + T - 1) / T, T>>>(n);
    k_hist<<<(e + T - 1) / T, T>>>(e);
    int nb = (n + 1023) / 1024;
    k_scanA<<<nb, 1024>>>(n);
    k_scanB<<<1, 32>>>(nb);
    k_scanC<<<(n + T - 1) / T, T>>>(n);
    k_fill<<<(e + T - 1) / T, T>>>(e);

    // --- layer 1 ---
    cudaFuncSetAttribute(k_gemm, cudaFuncAttributeMaxDynamicSharedMemorySize,
                         128 * 1024);
    int gblocks = (n + 127) / 128;
    k_gemm<<<gblocks, 256, 128 * 1024>>>(x, W1, ph, n);
    k_agg<<<(n * 32 + T - 1) / T, T>>>(ph, b1, pf, n);

    // --- layer 2 (embeddings straight into d_out) ---
    k_gemm<<<gblocks, 256, 128 * 1024>>>(pf, W2, ph, n);
    k_agg<<<(n * 32 + T - 1) / T, T>>>(ph, b2, emb, n);

    // --- FC head ---
    k_fc<<<(n * 32 + T - 1) / T, T>>>(emb, Wfc, bfc, out, n);
}

// round 2
// speedup vs baseline: 1.3019x; 1.3019x over previous
#include <cuda_runtime.h>
#include <cuda_bf16.h>
#include <math.h>

#define NN 100000
#define EE 1600000
#define DD 128
#define KP 68   // padded smem row stride in 32-bit words (136 bf16)

// ---------------- device scratch (no allocations allowed) ----------------
__device__ int   g_cnt[NN];
__device__ int   g_rowptr[NN];
__device__ int   g_cursor[NN];
__device__ float g_dinv[NN];
__device__ int   g_csrc[EE];
__device__ int   g_bsums[256];
__device__ int   g_is64;
__device__ float g_h[(size_t)NN * DD];
__device__ float g_f[(size_t)NN * DD];
__device__ __nv_bfloat16 g_wthi[2][DD * DD];   // W^T (n-major), hi part
__device__ __nv_bfloat16 g_wtlo[2][DD * DD];   // W^T lo part

// ---------------- edge dtype detection ----------------
__global__ void k_detect(const int* __restrict__ eb) {
    __shared__ int s_nz;
    if (threadIdx.x == 0) s_nz = 0;
    __syncthreads();
    int nz = 0;
    for (int i = threadIdx.x; i < 512; i += blockDim.x)
        nz += (eb[2 * i + 1] != 0);
    atomicAdd(&s_nz, nz);
    __syncthreads();
    if (threadIdx.x == 0) g_is64 = (s_nz == 0);
}

__global__ void k_zero(int n) {
    int i = blockIdx.x * blockDim.x + threadIdx.x;
    if (i < n) g_cnt[i] = 0;
}

// histogram of dst, reading edge buffer directly (int64 or int32 layout)
__global__ void k_hist(const int* __restrict__ eb, int e) {
    int i = blockIdx.x * blockDim.x + threadIdx.x;
    if (i >= e) return;
    int d = g_is64 ? eb[2 * (e + i)] : eb[e + i];
    atomicAdd(&g_cnt[d], 1);
}

__global__ void k_scanA(int n) {
    __shared__ int sh[1024];
    int gi = blockIdx.x * 1024 + threadIdx.x;
    int v = (gi < n) ? g_cnt[gi] : 0;
    sh[threadIdx.x] = v;
    __syncthreads();
    for (int off = 1; off < 1024; off <<= 1) {
        int x = sh[threadIdx.x];
        int y = (threadIdx.x >= off) ? sh[threadIdx.x - off] : 0;
        __syncthreads();
        sh[threadIdx.x] = x + y;
        __syncthreads();
    }
    int incl = sh[threadIdx.x];
    if (gi < n) g_rowptr[gi] = incl - v;
    if (threadIdx.x == 1023) g_bsums[blockIdx.x] = incl;
}

// parallel exclusive scan of block sums (single 128-thread block, nb <= 128)
__global__ void k_scanB(int nb) {
    __shared__ int sh[128];
    int v = (threadIdx.x < nb) ? g_bsums[threadIdx.x] : 0;
    sh[threadIdx.x] = v;
    __syncthreads();
    for (int off = 1; off < 128; off <<= 1) {
        int x = sh[threadIdx.x];
        int y = (threadIdx.x >= off) ? sh[threadIdx.x - off] : 0;
        __syncthreads();
        sh[threadIdx.x] = x + y;
        __syncthreads();
    }
    if (threadIdx.x < nb) g_bsums[threadIdx.x] = sh[threadIdx.x] - v;
}

__global__ void k_scanC(int n) {
    int i = blockIdx.x * blockDim.x + threadIdx.x;
    if (i >= n) return;
    int rp = g_rowptr[i] + g_bsums[i >> 10];
    g_rowptr[i] = rp;
    g_cursor[i] = rp;
    g_dinv[i] = rsqrtf((float)(g_cnt[i] + 1));
}

__global__ void k_fill(const int* __restrict__ eb, int e) {
    int i = blockIdx.x * blockDim.x + threadIdx.x;
    if (i >= e) return;
    int s, d;
    if (g_is64) { s = eb[2 * i]; d = eb[2 * (e + i)]; }
    else        { s = eb[i];     d = eb[e + i]; }
    int p = atomicAdd(&g_cursor[d], 1);
    g_csrc[p] = s;
}

// ---------------- weight convert: W[k][n] -> W^T hi/lo bf16 [n][k] ----------------
__global__ void k_convW(const float* __restrict__ W, int layer) {
    int i = blockIdx.x * blockDim.x + threadIdx.x;
    if (i >= DD * DD) return;
    int k = i >> 7, n = i & 127;
    float v = W[k * DD + n];
    __nv_bfloat16 hi = __float2bfloat16(v);
    float lo = v - __bfloat162float(hi);
    g_wthi[layer][n * DD + k] = hi;
    g_wtlo[layer][n * DD + k] = __float2bfloat16(lo);
}

// ---------------- tensor-core GEMM: C[n x 128] = A[n x 128] @ W ----------------
// mma.sync m16n8k16 bf16, 3-pass hi/lo split for ~fp32 accuracy.
// 256 threads = 8 warps (4x2), warp tile 32x64, block tile 128x128, K=128.
__device__ __forceinline__ void mma_bf16(float* d, const unsigned* a,
                                         unsigned b0, unsigned b1) {
    asm volatile(
        "mma.sync.aligned.m16n8k16.row.col.f32.bf16.bf16.f32 "
        "{%0,%1,%2,%3}, {%4,%5,%6,%7}, {%8,%9}, {%0,%1,%2,%3};\n"
        : "+f"(d[0]), "+f"(d[1]), "+f"(d[2]), "+f"(d[3])
        : "r"(a[0]), "r"(a[1]), "r"(a[2]), "r"(a[3]), "r"(b0), "r"(b1));
}

__global__ void __launch_bounds__(256) k_gemm_tc(
    const float* __restrict__ A,
    const __nv_bfloat16* __restrict__ Wthi,
    const __nv_bfloat16* __restrict__ Wtlo,
    float* __restrict__ C, int n) {
    extern __shared__ unsigned smu[];
    unsigned* Ahi = smu;
    unsigned* Alo = Ahi + 128 * KP;
    unsigned* Bhi = Alo + 128 * KP;
    unsigned* Blo = Bhi + 128 * KP;
    const int tid = threadIdx.x;
    const int row0 = blockIdx.x * 128;

    // W^T hi/lo (bf16, 32KB each) -> smem with pad
    {
        const uint4* sh = (const uint4*)Wthi;
        const uint4* sl = (const uint4*)Wtlo;
        for (int i = tid; i < 2048; i += 256) {
            int r = i >> 4, j = i & 15;
            ((uint4*)(Bhi + r * KP))[j] = sh[i];
            ((uint4*)(Blo + r * KP))[j] = sl[i];
        }
    }
    // A tile: fp32 load, split to bf16 hi/lo in smem
    {
        const float4* A4 = (const float4*)A;
        for (int i = tid; i < 4096; i += 256) {
            int r = i >> 5, j = i & 31;
            float4 v = make_float4(0.f, 0.f, 0.f, 0.f);
            if (row0 + r < n) v = A4[(size_t)(row0 + r) * 32 + j];
            __nv_bfloat16 h0 = __float2bfloat16(v.x), h1 = __float2bfloat16(v.y);
            __nv_bfloat16 h2 = __float2bfloat16(v.z), h3 = __float2bfloat16(v.w);
            float l0 = v.x - __bfloat162float(h0), l1 = v.y - __bfloat162float(h1);
            float l2 = v.z - __bfloat162float(h2), l3 = v.w - __bfloat162float(h3);
            unsigned hw0 = (unsigned)__bfloat16_as_ushort(h0) |
                           ((unsigned)__bfloat16_as_ushort(h1) << 16);
            unsigned hw1 = (unsigned)__bfloat16_as_ushort(h2) |
                           ((unsigned)__bfloat16_as_ushort(h3) << 16);
            __nv_bfloat16 g0 = __float2bfloat16(l0), g1 = __float2bfloat16(l1);
            __nv_bfloat16 g2 = __float2bfloat16(l2), g3 = __float2bfloat16(l3);
            unsigned lw0 = (unsigned)__bfloat16_as_ushort(g0) |
                           ((unsigned)__bfloat16_as_ushort(g1) << 16);
            unsigned lw1 = (unsigned)__bfloat16_as_ushort(g2) |
                           ((unsigned)__bfloat16_as_ushort(g3) << 16);
            *(uint2*)(Ahi + r * KP + 2 * j) = make_uint2(hw0, hw1);
            *(uint2*)(Alo + r * KP + 2 * j) = make_uint2(lw0, lw1);
        }
    }
    __syncthreads();

    const int wid = tid >> 5, lane = tid & 31;
    const int grp = lane >> 2, tig = lane & 3;
    const int mrow0 = (wid >> 1) * 32;   // warp M offset
    const int ncol0 = (wid & 1) * 64;    // warp N offset

    float acc[2][8][4];
#pragma unroll
    for (int mi = 0; mi < 2; mi++)
#pragma unroll
        for (int ni = 0; ni < 8; ni++)
#pragma unroll
            for (int q = 0; q < 4; q++) acc[mi][ni][q] = 0.f;

#pragma unroll
    for (int ks = 0; ks < 8; ks++) {
        const int kw = ks * 8 + tig;
        unsigned ah[2][4], al[2][4];
#pragma unroll
        for (int mi = 0; mi < 2; mi++) {
            int r0 = mrow0 + mi * 16 + grp;
            ah[mi][0] = Ahi[r0 * KP + kw];
            ah[mi][1] = Ahi[(r0 + 8) * KP + kw];
            ah[mi][2] = Ahi[r0 * KP + kw + 4];
            ah[mi][3] = Ahi[(r0 + 8) * KP + kw + 4];
            al[mi][0] = Alo[r0 * KP + kw];
            al[mi][1] = Alo[(r0 + 8) * KP + kw];
            al[mi][2] = Alo[r0 * KP + kw + 4];
            al[mi][3] = Alo[(r0 + 8) * KP + kw + 4];
        }
#pragma unroll
        for (int ni = 0; ni < 8; ni++) {
            int nr = ncol0 + ni * 8 + grp;
            unsigned bh0 = Bhi[nr * KP + kw], bh1 = Bhi[nr * KP + kw + 4];
            unsigned bl0 = Blo[nr * KP + kw], bl1 = Blo[nr * KP + kw + 4];
#pragma unroll
            for (int mi = 0; mi < 2; mi++) {
                mma_bf16(acc[mi][ni], ah[mi], bh0, bh1);
                mma_bf16(acc[mi][ni], ah[mi], bl0, bl1);
                mma_bf16(acc[mi][ni], al[mi], bh0, bh1);
            }
        }
    }

#pragma unroll
    for (int mi = 0; mi < 2; mi++)
#pragma unroll
        for (int ni = 0; ni < 8; ni++) {
            int r = row0 + mrow0 + mi * 16 + grp;
            int c = ncol0 + ni * 8 + tig * 2;
            if (r < n)
                *(float2*)(C + (size_t)r * DD + c) =
                    make_float2(acc[mi][ni][0], acc[mi][ni][1]);
            if (r + 8 < n)
                *(float2*)(C + (size_t)(r + 8) * DD + c) =
                    make_float2(acc[mi][ni][2], acc[mi][ni][3]);
        }
}

// ---------------- aggregation (gather-only CSR, one warp per node) ----------------
__global__ void __launch_bounds__(256) k_agg(const float* __restrict__ H,
                                             const float* __restrict__ b,
                                             float* __restrict__ out, int n) {
    int wid = (blockIdx.x * blockDim.x + threadIdx.x) >> 5;
    int lane = threadIdx.x & 31;
    if (wid >= n) return;
    const float4* H4 = (const float4*)H;
    float di = g_dinv[wid];
    float4 hv = H4[(size_t)wid * 32 + lane];
    float ax = di * hv.x, ay = di * hv.y, az = di * hv.z, aw = di * hv.w;

    int beg = g_rowptr[wid];
    int cnt = g_cnt[wid];
    int j = 0;
    for (; j + 2 <= cnt; j += 2) {
        int s0 = g_csrc[beg + j];
        int s1 = g_csrc[beg + j + 1];
        float w0 = g_dinv[s0];
        float w1 = g_dinv[s1];
        float4 v0 = H4[(size_t)s0 * 32 + lane];
        float4 v1 = H4[(size_t)s1 * 32 + lane];
        ax += w0 * v0.x + w1 * v1.x;
        ay += w0 * v0.y + w1 * v1.y;
        az += w0 * v0.z + w1 * v1.z;
        aw += w0 * v0.w + w1 * v1.w;
    }
    if (j < cnt) {
        int s0 = g_csrc[beg + j];
        float w0 = g_dinv[s0];
        float4 v0 = H4[(size_t)s0 * 32 + lane];
        ax += w0 * v0.x;
        ay += w0 * v0.y;
        az += w0 * v0.z;
        aw += w0 * v0.w;
    }
    float4 bb = ((const float4*)b)[lane];
    float4 o;
    o.x = tanhf(di * ax + bb.x);
    o.y = tanhf(di * ay + bb.y);
    o.z = tanhf(di * az + bb.z);
    o.w = tanhf(di * aw + bb.w);
    ((float4*)out)[(size_t)wid * 32 + lane] = o;
}

// ---------------- FC head ----------------
__global__ void __launch_bounds__(256) k_fc(const float* __restrict__ emb,
                                            const float* __restrict__ Wfc,
                                            const float* __restrict__ bfc,
                                            float* __restrict__ out, int n) {
    int wid = (blockIdx.x * blockDim.x + threadIdx.x) >> 5;
    int lane = threadIdx.x & 31;
    if (wid >= n) return;
    float4 e = ((const float4*)emb)[(size_t)wid * 32 + lane];
    float4 w = ((const float4*)Wfc)[lane];
    float s = e.x * w.x + e.y * w.y + e.z * w.z + e.w * w.w;
#pragma unroll
    for (int o = 16; o; o >>= 1) s += __shfl_xor_sync(0xFFFFFFFFu, s, o);
    if (lane == 0) out[wid] = 1.0f / (1.0f + expf(-(s + bfc[0])));
}

// ---------------- launch ----------------
extern "C" void kernel_launch(void* const* d_in, const int* in_sizes, int n_in,
                              void* d_out, int out_size) {
    const float* x   = (const float*)d_in[0];
    const int*   eb  = (const int*)d_in[1];
    const float* W1  = (const float*)d_in[2];
    const float* b1  = (const float*)d_in[3];
    const float* W2  = (const float*)d_in[4];
    const float* b2  = (const float*)d_in[5];
    const float* Wfc = (const float*)d_in[6];
    const float* bfc = (const float*)d_in[7];

    int n = in_sizes[0] / DD;
    int e = in_sizes[1] / 2;

    float* out = (float*)d_out;
    float* emb = out + n;

    float *ph, *pf;
    cudaGetSymbolAddress((void**)&ph, g_h);
    cudaGetSymbolAddress((void**)&pf, g_f);
    __nv_bfloat16 *w1h, *w1l, *w2h, *w2l;
    cudaGetSymbolAddress((void**)&w1h, g_wthi);
    cudaGetSymbolAddress((void**)&w1l, g_wtlo);
    w2h = w1h + DD * DD;
    w2l = w1l + DD * DD;

    static int smem_set = 0;
    const int gemm_smem = 4 * 128 * KP * 4;  // 139,264 B
    if (!smem_set) {
        cudaFuncSetAttribute(k_gemm_tc,
                             cudaFuncAttributeMaxDynamicSharedMemorySize,
                             gemm_smem);
        smem_set = 1;
    }

    const int T = 256;
    // --- graph preprocessing ---
    k_detect<<<1, 256>>>(eb);
    k_zero<<<(n + T - 1) / T, T>>>(n);
    k_hist<<<(e + T - 1) / T, T>>>(eb, e);
    int nb = (n + 1023) / 1024;
    k_scanA<<<nb, 1024>>>(n);
    k_scanB<<<1, 128>>>(nb);
    k_scanC<<<(n + T - 1) / T, T>>>(n);
    k_fill<<<(e + T - 1) / T, T>>>(eb, e);

    // --- weight conversion (both layers) ---
    k_convW<<<64, 256>>>(W1, 0);
    k_convW<<<64, 256>>>(W2, 1);

    int gblocks = (n + 127) / 128;
    // --- layer 1 ---
    k_gemm_tc<<<gblocks, 256, gemm_smem>>>(x, w1h, w1l, ph, n);
    k_agg<<<(n * 32 + T - 1) / T, T>>>(ph, b1, pf, n);
    // --- layer 2 ---
    k_gemm_tc<<<gblocks, 256, gemm_smem>>>(pf, w2h, w2l, ph, n);
    k_agg<<<(n * 32 + T - 1) / T, T>>>(ph, b2, emb, n);
    // --- FC head ---
    k_fc<<<(n * 32 + T - 1) / T, T>>>(emb, Wfc, bfc, out, n);
}

// round 3
// speedup vs baseline: 1.5747x; 1.2095x over previous
#include <cuda_runtime.h>
#include <cuda_bf16.h>
#include <cuda_fp16.h>
#include <math.h>

#define NN 100000
#define EE 1600000
#define DD 128
#define KP 68   // padded smem row stride in 32-bit words (136 bf16)

// ---------------- device scratch (no allocations allowed) ----------------
__device__ int    g_cnt[NN];
__device__ int    g_rowptr[NN];
__device__ int    g_cursor[NN];
__device__ float  g_dinv[NN];
__device__ int    g_csrc[EE];
__device__ int    g_bsums[256];
__device__ int    g_is64;
__device__ __half g_a16[(size_t)NN * DD];  // GEMM output in fp16 (gather source)
__device__ float  g_f[(size_t)NN * DD];    // layer-1 activations (fp32)
__device__ __nv_bfloat16 g_wthi[2][DD * DD];
__device__ __nv_bfloat16 g_wtlo[2][DD * DD];

// ---------------- edge dtype detection ----------------
__global__ void k_detect(const int* __restrict__ eb) {
    __shared__ int s_nz;
    if (threadIdx.x == 0) s_nz = 0;
    __syncthreads();
    int nz = 0;
    for (int i = threadIdx.x; i < 512; i += blockDim.x)
        nz += (eb[2 * i + 1] != 0);
    atomicAdd(&s_nz, nz);
    __syncthreads();
    if (threadIdx.x == 0) g_is64 = (s_nz == 0);
}

__global__ void k_hist(const int* __restrict__ eb, int e) {
    int i = blockIdx.x * blockDim.x + threadIdx.x;
    if (i >= e) return;
    int d = g_is64 ? eb[2 * (e + i)] : eb[e + i];
    atomicAdd(&g_cnt[d], 1);
}

__global__ void k_scanA(int n) {
    __shared__ int sh[1024];
    int gi = blockIdx.x * 1024 + threadIdx.x;
    int v = (gi < n) ? g_cnt[gi] : 0;
    sh[threadIdx.x] = v;
    __syncthreads();
    for (int off = 1; off < 1024; off <<= 1) {
        int x = sh[threadIdx.x];
        int y = (threadIdx.x >= off) ? sh[threadIdx.x - off] : 0;
        __syncthreads();
        sh[threadIdx.x] = x + y;
        __syncthreads();
    }
    int incl = sh[threadIdx.x];
    if (gi < n) g_rowptr[gi] = incl - v;
    if (threadIdx.x == 1023) g_bsums[blockIdx.x] = incl;
}

__global__ void k_scanB(int nb) {
    __shared__ int sh[128];
    int v = (threadIdx.x < nb) ? g_bsums[threadIdx.x] : 0;
    sh[threadIdx.x] = v;
    __syncthreads();
    for (int off = 1; off < 128; off <<= 1) {
        int x = sh[threadIdx.x];
        int y = (threadIdx.x >= off) ? sh[threadIdx.x - off] : 0;
        __syncthreads();
        sh[threadIdx.x] = x + y;
        __syncthreads();
    }
    if (threadIdx.x < nb) g_bsums[threadIdx.x] = sh[threadIdx.x] - v;
}

__global__ void k_scanC(int n) {
    int i = blockIdx.x * blockDim.x + threadIdx.x;
    if (i >= n) return;
    int rp = g_rowptr[i] + g_bsums[i >> 10];
    g_rowptr[i] = rp;
    g_cursor[i] = rp;
    g_dinv[i] = rsqrtf((float)(g_cnt[i] + 1));
}

__global__ void k_fill(const int* __restrict__ eb, int e) {
    int i = blockIdx.x * blockDim.x + threadIdx.x;
    if (i >= e) return;
    int s, d;
    if (g_is64) { s = eb[2 * i]; d = eb[2 * (e + i)]; }
    else        { s = eb[i];     d = eb[e + i]; }
    int p = atomicAdd(&g_cursor[d], 1);
    g_csrc[p] = s;
}

// ---------------- weight convert: W[k][n] -> W^T hi/lo bf16 [n][k] ----------------
__global__ void k_convW(const float* __restrict__ W, int layer) {
    int i = blockIdx.x * blockDim.x + threadIdx.x;
    if (i >= DD * DD) return;
    int k = i >> 7, n = i & 127;
    float v = W[k * DD + n];
    __nv_bfloat16 hi = __float2bfloat16(v);
    float lo = v - __bfloat162float(hi);
    g_wthi[layer][n * DD + k] = hi;
    g_wtlo[layer][n * DD + k] = __float2bfloat16(lo);
}

// ---------------- tensor-core GEMM -> fp16 output ----------------
__device__ __forceinline__ void mma_bf16(float* d, const unsigned* a,
                                         unsigned b0, unsigned b1) {
    asm volatile(
        "mma.sync.aligned.m16n8k16.row.col.f32.bf16.bf16.f32 "
        "{%0,%1,%2,%3}, {%4,%5,%6,%7}, {%8,%9}, {%0,%1,%2,%3};\n"
        : "+f"(d[0]), "+f"(d[1]), "+f"(d[2]), "+f"(d[3])
        : "r"(a[0]), "r"(a[1]), "r"(a[2]), "r"(a[3]), "r"(b0), "r"(b1));
}

__global__ void __launch_bounds__(256) k_gemm_tc(
    const float* __restrict__ A,
    const __nv_bfloat16* __restrict__ Wthi,
    const __nv_bfloat16* __restrict__ Wtlo,
    __half* __restrict__ C, int n) {
    extern __shared__ unsigned smu[];
    unsigned* Ahi = smu;
    unsigned* Alo = Ahi + 128 * KP;
    unsigned* Bhi = Alo + 128 * KP;
    unsigned* Blo = Bhi + 128 * KP;
    const int tid = threadIdx.x;
    const int row0 = blockIdx.x * 128;

    {
        const uint4* sh = (const uint4*)Wthi;
        const uint4* sl = (const uint4*)Wtlo;
        for (int i = tid; i < 2048; i += 256) {
            int r = i >> 4, j = i & 15;
            ((uint4*)(Bhi + r * KP))[j] = sh[i];
            ((uint4*)(Blo + r * KP))[j] = sl[i];
        }
    }
    {
        const float4* A4 = (const float4*)A;
        for (int i = tid; i < 4096; i += 256) {
            int r = i >> 5, j = i & 31;
            float4 v = make_float4(0.f, 0.f, 0.f, 0.f);
            if (row0 + r < n) v = A4[(size_t)(row0 + r) * 32 + j];
            __nv_bfloat16 h0 = __float2bfloat16(v.x), h1 = __float2bfloat16(v.y);
            __nv_bfloat16 h2 = __float2bfloat16(v.z), h3 = __float2bfloat16(v.w);
            float l0 = v.x - __bfloat162float(h0), l1 = v.y - __bfloat162float(h1);
            float l2 = v.z - __bfloat162float(h2), l3 = v.w - __bfloat162float(h3);
            unsigned hw0 = (unsigned)__bfloat16_as_ushort(h0) |
                           ((unsigned)__bfloat16_as_ushort(h1) << 16);
            unsigned hw1 = (unsigned)__bfloat16_as_ushort(h2) |
                           ((unsigned)__bfloat16_as_ushort(h3) << 16);
            __nv_bfloat16 g0 = __float2bfloat16(l0), g1 = __float2bfloat16(l1);
            __nv_bfloat16 g2 = __float2bfloat16(l2), g3 = __float2bfloat16(l3);
            unsigned lw0 = (unsigned)__bfloat16_as_ushort(g0) |
                           ((unsigned)__bfloat16_as_ushort(g1) << 16);
            unsigned lw1 = (unsigned)__bfloat16_as_ushort(g2) |
                           ((unsigned)__bfloat16_as_ushort(g3) << 16);
            *(uint2*)(Ahi + r * KP + 2 * j) = make_uint2(hw0, hw1);
            *(uint2*)(Alo + r * KP + 2 * j) = make_uint2(lw0, lw1);
        }
    }
    __syncthreads();

    const int wid = tid >> 5, lane = tid & 31;
    const int grp = lane >> 2, tig = lane & 3;
    const int mrow0 = (wid >> 1) * 32;
    const int ncol0 = (wid & 1) * 64;

    float acc[2][8][4];
#pragma unroll
    for (int mi = 0; mi < 2; mi++)
#pragma unroll
        for (int ni = 0; ni < 8; ni++)
#pragma unroll
            for (int q = 0; q < 4; q++) acc[mi][ni][q] = 0.f;

#pragma unroll
    for (int ks = 0; ks < 8; ks++) {
        const int kw = ks * 8 + tig;
        unsigned ah[2][4], al[2][4];
#pragma unroll
        for (int mi = 0; mi < 2; mi++) {
            int r0 = mrow0 + mi * 16 + grp;
            ah[mi][0] = Ahi[r0 * KP + kw];
            ah[mi][1] = Ahi[(r0 + 8) * KP + kw];
            ah[mi][2] = Ahi[r0 * KP + kw + 4];
            ah[mi][3] = Ahi[(r0 + 8) * KP + kw + 4];
            al[mi][0] = Alo[r0 * KP + kw];
            al[mi][1] = Alo[(r0 + 8) * KP + kw];
            al[mi][2] = Alo[r0 * KP + kw + 4];
            al[mi][3] = Alo[(r0 + 8) * KP + kw + 4];
        }
#pragma unroll
        for (int ni = 0; ni < 8; ni++) {
            int nr = ncol0 + ni * 8 + grp;
            unsigned bh0 = Bhi[nr * KP + kw], bh1 = Bhi[nr * KP + kw + 4];
            unsigned bl0 = Blo[nr * KP + kw], bl1 = Blo[nr * KP + kw + 4];
#pragma unroll
            for (int mi = 0; mi < 2; mi++) {
                mma_bf16(acc[mi][ni], ah[mi], bh0, bh1);
                mma_bf16(acc[mi][ni], ah[mi], bl0, bl1);
                mma_bf16(acc[mi][ni], al[mi], bh0, bh1);
            }
        }
    }

#pragma unroll
    for (int mi = 0; mi < 2; mi++) {
        int r = row0 + mrow0 + mi * 16 + grp;
#pragma unroll
        for (int ni = 0; ni < 8; ni++) {
            int c = ncol0 + ni * 8 + tig * 2;
            if (r < n)
                *(__half2*)(C + (size_t)r * DD + c) =
                    __floats2half2_rn(acc[mi][ni][0], acc[mi][ni][1]);
            if (r + 8 < n)
                *(__half2*)(C + (size_t)(r + 8) * DD + c) =
                    __floats2half2_rn(acc[mi][ni][2], acc[mi][ni][3]);
        }
    }
}

// ---------------- aggregation (fp16 gather, one warp per node) ----------------
// t = sum_{s in in(d)} dinv[s]*h[s]  +  dinv[d]*h[d]
// out[d] = tanh(dinv[d]*t + b);  optional fused FC head (layer 2).
__global__ void __launch_bounds__(256) k_agg16(const __half* __restrict__ H,
                                               const float* __restrict__ b,
                                               float* __restrict__ out,
                                               const float* __restrict__ Wfc,
                                               const float* __restrict__ bfc,
                                               float* __restrict__ fcout,
                                               int n) {
    int wid = (blockIdx.x * blockDim.x + threadIdx.x) >> 5;
    int lane = threadIdx.x & 31;
    if (wid >= n) return;
    const uint2* H2 = (const uint2*)H;   // 4 halves per lane, row stride 32
    float di = g_dinv[wid];

    uint2 us = H2[(size_t)wid * 32 + lane];
    float2 s0f = __half22float2(*(__half2*)&us.x);
    float2 s1f = __half22float2(*(__half2*)&us.y);
    float ax = di * s0f.x, ay = di * s0f.y, az = di * s1f.x, aw = di * s1f.y;

    int beg = g_rowptr[wid];
    int cnt = g_cnt[wid];
    int j = 0;
    for (; j + 2 <= cnt; j += 2) {
        int n0 = g_csrc[beg + j];
        int n1 = g_csrc[beg + j + 1];
        float w0 = g_dinv[n0];
        float w1 = g_dinv[n1];
        uint2 u0 = H2[(size_t)n0 * 32 + lane];
        uint2 u1 = H2[(size_t)n1 * 32 + lane];
        float2 a0 = __half22float2(*(__half2*)&u0.x);
        float2 a1 = __half22float2(*(__half2*)&u0.y);
        float2 b0 = __half22float2(*(__half2*)&u1.x);
        float2 b1 = __half22float2(*(__half2*)&u1.y);
        ax += w0 * a0.x + w1 * b0.x;
        ay += w0 * a0.y + w1 * b0.y;
        az += w0 * a1.x + w1 * b1.x;
        aw += w0 * a1.y + w1 * b1.y;
    }
    if (j < cnt) {
        int n0 = g_csrc[beg + j];
        float w0 = g_dinv[n0];
        uint2 u0 = H2[(size_t)n0 * 32 + lane];
        float2 a0 = __half22float2(*(__half2*)&u0.x);
        float2 a1 = __half22float2(*(__half2*)&u0.y);
        ax += w0 * a0.x;
        ay += w0 * a0.y;
        az += w0 * a1.x;
        aw += w0 * a1.y;
    }
    float4 bb = ((const float4*)b)[lane];
    float ox = tanhf(di * ax + bb.x);
    float oy = tanhf(di * ay + bb.y);
    float oz = tanhf(di * az + bb.z);
    float ow = tanhf(di * aw + bb.w);
    ((float4*)out)[(size_t)wid * 32 + lane] = make_float4(ox, oy, oz, ow);

    if (fcout) {
        float4 w = ((const float4*)Wfc)[lane];
        float s = ox * w.x + oy * w.y + oz * w.z + ow * w.w;
#pragma unroll
        for (int o = 16; o; o >>= 1) s += __shfl_xor_sync(0xFFFFFFFFu, s, o);
        if (lane == 0) fcout[wid] = 1.0f / (1.0f + expf(-(s + bfc[0])));
    }
}

// ---------------- launch ----------------
extern "C" void kernel_launch(void* const* d_in, const int* in_sizes, int n_in,
                              void* d_out, int out_size) {
    const float* x   = (const float*)d_in[0];
    const int*   eb  = (const int*)d_in[1];
    const float* W1  = (const float*)d_in[2];
    const float* b1  = (const float*)d_in[3];
    const float* W2  = (const float*)d_in[4];
    const float* b2  = (const float*)d_in[5];
    const float* Wfc = (const float*)d_in[6];
    const float* bfc = (const float*)d_in[7];

    int n = in_sizes[0] / DD;
    int e = in_sizes[1] / 2;

    float* out = (float*)d_out;
    float* emb = out + n;

    __half* pa;
    float* pf;
    int* pcnt;
    cudaGetSymbolAddress((void**)&pa, g_a16);
    cudaGetSymbolAddress((void**)&pf, g_f);
    cudaGetSymbolAddress((void**)&pcnt, g_cnt);
    __nv_bfloat16 *w1h, *w1l, *w2h, *w2l;
    cudaGetSymbolAddress((void**)&w1h, g_wthi);
    cudaGetSymbolAddress((void**)&w1l, g_wtlo);
    w2h = w1h + DD * DD;
    w2l = w1l + DD * DD;

    static cudaStream_t s1 = nullptr;
    static cudaEvent_t evF = nullptr, evJ = nullptr;
    static int smem_set = 0;
    const int gemm_smem = 4 * 128 * KP * 4;
    if (!smem_set) {
        cudaFuncSetAttribute(k_gemm_tc,
                             cudaFuncAttributeMaxDynamicSharedMemorySize,
                             gemm_smem);
        cudaStreamCreateWithFlags(&s1, cudaStreamNonBlocking);
        cudaEventCreateWithFlags(&evF, cudaEventDisableTiming);
        cudaEventCreateWithFlags(&evJ, cudaEventDisableTiming);
        smem_set = 1;
    }

    const int T = 256;
    int nb = (n + 1023) / 1024;
    int gblocks = (n + 127) / 128;

    // --- fork: CSR preprocessing on s1, GEMM path on default stream ---
    cudaEventRecord(evF, 0);
    cudaStreamWaitEvent(s1, evF, 0);

    cudaMemsetAsync(pcnt, 0, (size_t)n * sizeof(int), s1);
    k_detect<<<1, 256, 0, s1>>>(eb);
    k_hist<<<(e + T - 1) / T, T, 0, s1>>>(eb, e);
    k_scanA<<<nb, 1024, 0, s1>>>(n);
    k_scanB<<<1, 128, 0, s1>>>(nb);
    k_scanC<<<(n + T - 1) / T, T, 0, s1>>>(n);
    k_fill<<<(e + T - 1) / T, T, 0, s1>>>(eb, e);
    cudaEventRecord(evJ, s1);

    k_convW<<<64, 256>>>(W1, 0);
    k_convW<<<64, 256>>>(W2, 1);
    k_gemm_tc<<<gblocks, 256, gemm_smem>>>(x, w1h, w1l, pa, n);

    cudaStreamWaitEvent(0, evJ, 0);

    // --- layer 1 ---
    k_agg16<<<(n * 32 + T - 1) / T, T>>>(pa, b1, pf, nullptr, nullptr, nullptr, n);
    // --- layer 2 + fused FC head ---
    k_gemm_tc<<<gblocks, 256, gemm_smem>>>(pf, w2h, w2l, pa, n);
    k_agg16<<<(n * 32 + T - 1) / T, T>>>(pa, b2, emb, Wfc, bfc, out, n);
}

// round 4
// speedup vs baseline: 1.5894x; 1.0093x over previous
#include <cuda_runtime.h>
#include <cuda_bf16.h>
#include <cuda_fp16.h>
#include <math.h>

#define NN 100000
#define EE 1600000
#define DD 128
#define KP 68   // padded smem row stride in 32-bit words

// ---------------- device scratch (no allocations allowed) ----------------
__device__ int    g_cnt[NN];
__device__ int    g_rowptr[NN];
__device__ int    g_cursor[NN];
__device__ float  g_dinv[NN];
__device__ int2   g_cedge[EE];             // packed (src, dinv[src] bits)
__device__ int    g_bsums[256];
__device__ int    g_is64;
__device__ __half g_a16[(size_t)NN * DD];  // GEMM output (gather source)
__device__ __half g_f16[(size_t)NN * DD];  // layer-1 activations
__device__ __nv_bfloat16 g_wthi[2][DD * DD];
__device__ __nv_bfloat16 g_wtlo[2][DD * DD];

// ---------------- edge dtype detection ----------------
__global__ void k_detect(const int* __restrict__ eb) {
    __shared__ int s_nz;
    if (threadIdx.x == 0) s_nz = 0;
    __syncthreads();
    int nz = 0;
    for (int i = threadIdx.x; i < 512; i += blockDim.x)
        nz += (eb[2 * i + 1] != 0);
    atomicAdd(&s_nz, nz);
    __syncthreads();
    if (threadIdx.x == 0) g_is64 = (s_nz == 0);
}

__global__ void k_hist(const int* __restrict__ eb, int e) {
    int i = blockIdx.x * blockDim.x + threadIdx.x;
    if (i >= e) return;
    int d = g_is64 ? eb[2 * (e + i)] : eb[e + i];
    atomicAdd(&g_cnt[d], 1);
}

__global__ void k_scanA(int n) {
    __shared__ int sh[1024];
    int gi = blockIdx.x * 1024 + threadIdx.x;
    int v = (gi < n) ? g_cnt[gi] : 0;
    sh[threadIdx.x] = v;
    __syncthreads();
    for (int off = 1; off < 1024; off <<= 1) {
        int x = sh[threadIdx.x];
        int y = (threadIdx.x >= off) ? sh[threadIdx.x - off] : 0;
        __syncthreads();
        sh[threadIdx.x] = x + y;
        __syncthreads();
    }
    int incl = sh[threadIdx.x];
    if (gi < n) g_rowptr[gi] = incl - v;
    if (threadIdx.x == 1023) g_bsums[blockIdx.x] = incl;
}

__global__ void k_scanB(int nb) {
    __shared__ int sh[128];
    int v = (threadIdx.x < nb) ? g_bsums[threadIdx.x] : 0;
    sh[threadIdx.x] = v;
    __syncthreads();
    for (int off = 1; off < 128; off <<= 1) {
        int x = sh[threadIdx.x];
        int y = (threadIdx.x >= off) ? sh[threadIdx.x - off] : 0;
        __syncthreads();
        sh[threadIdx.x] = x + y;
        __syncthreads();
    }
    if (threadIdx.x < nb) g_bsums[threadIdx.x] = sh[threadIdx.x] - v;
}

__global__ void k_scanC(int n) {
    int i = blockIdx.x * blockDim.x + threadIdx.x;
    if (i >= n) return;
    int rp = g_rowptr[i] + g_bsums[i >> 10];
    g_rowptr[i] = rp;
    g_cursor[i] = rp;
    g_dinv[i] = rsqrtf((float)(g_cnt[i] + 1));
}

__global__ void k_fill(const int* __restrict__ eb, int e) {
    int i = blockIdx.x * blockDim.x + threadIdx.x;
    if (i >= e) return;
    int s, d;
    if (g_is64) { s = eb[2 * i]; d = eb[2 * (e + i)]; }
    else        { s = eb[i];     d = eb[e + i]; }
    int p = atomicAdd(&g_cursor[d], 1);
    g_cedge[p] = make_int2(s, __float_as_int(g_dinv[s]));
}

// ---------------- weight convert (both layers in one launch) ----------------
__global__ void k_convW(const float* __restrict__ WA,
                        const float* __restrict__ WB) {
    int i = blockIdx.x * blockDim.x + threadIdx.x;
    if (i >= 2 * DD * DD) return;
    int layer = i >> 14;
    int r = i & (DD * DD - 1);
    int k = r >> 7, n = r & 127;
    const float* W = layer ? WB : WA;
    float v = W[k * DD + n];
    __nv_bfloat16 hi = __float2bfloat16(v);
    float lo = v - __bfloat162float(hi);
    g_wthi[layer][n * DD + k] = hi;
    g_wtlo[layer][n * DD + k] = __float2bfloat16(lo);
}

// ---------------- tensor-core GEMM -> fp16 output ----------------
__device__ __forceinline__ void mma_bf16(float* d, const unsigned* a,
                                         unsigned b0, unsigned b1) {
    asm volatile(
        "mma.sync.aligned.m16n8k16.row.col.f32.bf16.bf16.f32 "
        "{%0,%1,%2,%3}, {%4,%5,%6,%7}, {%8,%9}, {%0,%1,%2,%3};\n"
        : "+f"(d[0]), "+f"(d[1]), "+f"(d[2]), "+f"(d[3])
        : "r"(a[0]), "r"(a[1]), "r"(a[2]), "r"(a[3]), "r"(b0), "r"(b1));
}

__global__ void __launch_bounds__(256) k_gemm_tc(
    const void* __restrict__ Ain, int a_half,
    const __nv_bfloat16* __restrict__ Wthi,
    const __nv_bfloat16* __restrict__ Wtlo,
    __half* __restrict__ C, int n) {
    extern __shared__ unsigned smu[];
    unsigned* Ahi = smu;
    unsigned* Alo = Ahi + 128 * KP;
    unsigned* Bhi = Alo + 128 * KP;
    unsigned* Blo = Bhi + 128 * KP;
    const int tid = threadIdx.x;
    const int row0 = blockIdx.x * 128;

    {
        const uint4* sh = (const uint4*)Wthi;
        const uint4* sl = (const uint4*)Wtlo;
        for (int i = tid; i < 2048; i += 256) {
            int r = i >> 4, j = i & 15;
            ((uint4*)(Bhi + r * KP))[j] = sh[i];
            ((uint4*)(Blo + r * KP))[j] = sl[i];
        }
    }
    {
        const float4* A4 = (const float4*)Ain;
        const uint2* A2 = (const uint2*)Ain;
        for (int i = tid; i < 4096; i += 256) {
            int r = i >> 5, j = i & 31;
            float4 v = make_float4(0.f, 0.f, 0.f, 0.f);
            if (row0 + r < n) {
                if (a_half) {
                    uint2 hh = A2[(size_t)(row0 + r) * 32 + j];
                    float2 f0 = __half22float2(*(__half2*)&hh.x);
                    float2 f1 = __half22float2(*(__half2*)&hh.y);
                    v = make_float4(f0.x, f0.y, f1.x, f1.y);
                } else {
                    v = A4[(size_t)(row0 + r) * 32 + j];
                }
            }
            __nv_bfloat16 h0 = __float2bfloat16(v.x), h1 = __float2bfloat16(v.y);
            __nv_bfloat16 h2 = __float2bfloat16(v.z), h3 = __float2bfloat16(v.w);
            float l0 = v.x - __bfloat162float(h0), l1 = v.y - __bfloat162float(h1);
            float l2 = v.z - __bfloat162float(h2), l3 = v.w - __bfloat162float(h3);
            unsigned hw0 = (unsigned)__bfloat16_as_ushort(h0) |
                           ((unsigned)__bfloat16_as_ushort(h1) << 16);
            unsigned hw1 = (unsigned)__bfloat16_as_ushort(h2) |
                           ((unsigned)__bfloat16_as_ushort(h3) << 16);
            __nv_bfloat16 g0 = __float2bfloat16(l0), g1 = __float2bfloat16(l1);
            __nv_bfloat16 g2 = __float2bfloat16(l2), g3 = __float2bfloat16(l3);
            unsigned lw0 = (unsigned)__bfloat16_as_ushort(g0) |
                           ((unsigned)__bfloat16_as_ushort(g1) << 16);
            unsigned lw1 = (unsigned)__bfloat16_as_ushort(g2) |
                           ((unsigned)__bfloat16_as_ushort(g3) << 16);
            *(uint2*)(Ahi + r * KP + 2 * j) = make_uint2(hw0, hw1);
            *(uint2*)(Alo + r * KP + 2 * j) = make_uint2(lw0, lw1);
        }
    }
    __syncthreads();

    const int wid = tid >> 5, lane = tid & 31;
    const int grp = lane >> 2, tig = lane & 3;
    const int mrow0 = (wid >> 1) * 32;
    const int ncol0 = (wid & 1) * 64;

    float acc[2][8][4];
#pragma unroll
    for (int mi = 0; mi < 2; mi++)
#pragma unroll
        for (int ni = 0; ni < 8; ni++)
#pragma unroll
            for (int q = 0; q < 4; q++) acc[mi][ni][q] = 0.f;

#pragma unroll
    for (int ks = 0; ks < 8; ks++) {
        const int kw = ks * 8 + tig;
        unsigned ah[2][4], al[2][4];
#pragma unroll
        for (int mi = 0; mi < 2; mi++) {
            int r0 = mrow0 + mi * 16 + grp;
            ah[mi][0] = Ahi[r0 * KP + kw];
            ah[mi][1] = Ahi[(r0 + 8) * KP + kw];
            ah[mi][2] = Ahi[r0 * KP + kw + 4];
            ah[mi][3] = Ahi[(r0 + 8) * KP + kw + 4];
            al[mi][0] = Alo[r0 * KP + kw];
            al[mi][1] = Alo[(r0 + 8) * KP + kw];
            al[mi][2] = Alo[r0 * KP + kw + 4];
            al[mi][3] = Alo[(r0 + 8) * KP + kw + 4];
        }
#pragma unroll
        for (int ni = 0; ni < 8; ni++) {
            int nr = ncol0 + ni * 8 + grp;
            unsigned bh0 = Bhi[nr * KP + kw], bh1 = Bhi[nr * KP + kw + 4];
            unsigned bl0 = Blo[nr * KP + kw], bl1 = Blo[nr * KP + kw + 4];
#pragma unroll
            for (int mi = 0; mi < 2; mi++) {
                mma_bf16(acc[mi][ni], ah[mi], bh0, bh1);
                mma_bf16(acc[mi][ni], ah[mi], bl0, bl1);
                mma_bf16(acc[mi][ni], al[mi], bh0, bh1);
            }
        }
    }

#pragma unroll
    for (int mi = 0; mi < 2; mi++) {
        int r = row0 + mrow0 + mi * 16 + grp;
#pragma unroll
        for (int ni = 0; ni < 8; ni++) {
            int c = ncol0 + ni * 8 + tig * 2;
            if (r < n)
                *(__half2*)(C + (size_t)r * DD + c) =
                    __floats2half2_rn(acc[mi][ni][0], acc[mi][ni][1]);
            if (r + 8 < n)
                *(__half2*)(C + (size_t)(r + 8) * DD + c) =
                    __floats2half2_rn(acc[mi][ni][2], acc[mi][ni][3]);
        }
    }
}

// ---------------- aggregation v2 ----------------
// One warp per node, split into 2 edge-slots of 16 lanes; each lane owns 8
// features (uint4 = 8 halves). Edge (src, weight) preloaded coalesced and
// shfl-broadcast -> no dependent loads in the gather chain.
__device__ __forceinline__ void acc8(float* a, uint4 u, float w) {
    float2 f;
    f = __half22float2(*(__half2*)&u.x); a[0] += w * f.x; a[1] += w * f.y;
    f = __half22float2(*(__half2*)&u.y); a[2] += w * f.x; a[3] += w * f.y;
    f = __half22float2(*(__half2*)&u.z); a[4] += w * f.x; a[5] += w * f.y;
    f = __half22float2(*(__half2*)&u.w); a[6] += w * f.x; a[7] += w * f.y;
}

__global__ void __launch_bounds__(256) k_agg16(
    const __half* __restrict__ H, const float* __restrict__ b,
    __half* __restrict__ outh, float* __restrict__ outf,
    const float* __restrict__ Wfc, const float* __restrict__ bfc,
    float* __restrict__ fcout, int n) {
    const unsigned FULL = 0xFFFFFFFFu;
    int node = (blockIdx.x * blockDim.x + threadIdx.x) >> 5;
    int lane = threadIdx.x & 31;
    if (node >= n) return;
    int p = lane >> 4, c = lane & 15;
    const uint4* H4 = (const uint4*)H;
    float di = g_dinv[node];

    float acc[8];
    {
        uint4 u = H4[(size_t)node * 16 + c];
        float w = (p == 0) ? di : 0.f;
        float2 f;
        f = __half22float2(*(__half2*)&u.x); acc[0] = w * f.x; acc[1] = w * f.y;
        f = __half22float2(*(__half2*)&u.y); acc[2] = w * f.x; acc[3] = w * f.y;
        f = __half22float2(*(__half2*)&u.z); acc[4] = w * f.x; acc[5] = w * f.y;
        f = __half22float2(*(__half2*)&u.w); acc[6] = w * f.x; acc[7] = w * f.y;
    }

    int beg = g_rowptr[node];
    int cnt = g_cnt[node];
    int done = 0;
    while (done < cnt) {
        int m = cnt - done;
        if (m > 32) m = 32;
        int idx = 0;
        float wv = 0.f;
        if (lane < m) {
            int2 ew = g_cedge[beg + done + lane];
            idx = ew.x;
            wv = __int_as_float(ew.y);
        }
        int j = 0;
        for (; j + 4 <= m; j += 4) {
            int e0 = j + p, e1 = j + 2 + p;
            int i0 = __shfl_sync(FULL, idx, e0);
            float w0 = __shfl_sync(FULL, wv, e0);
            int i1 = __shfl_sync(FULL, idx, e1);
            float w1 = __shfl_sync(FULL, wv, e1);
            uint4 u0 = H4[(size_t)i0 * 16 + c];
            uint4 u1 = H4[(size_t)i1 * 16 + c];
            acc8(acc, u0, w0);
            acc8(acc, u1, w1);
        }
        if (j < m) {
            int e = j + p;
            int i0 = __shfl_sync(FULL, idx, e & 31);
            float w0 = __shfl_sync(FULL, wv, e & 31);
            if (e < m) {
                uint4 u0 = H4[(size_t)i0 * 16 + c];
                acc8(acc, u0, w0);
            }
            j += 2;
            if (j < m) {
                e = j + p;
                i0 = __shfl_sync(FULL, idx, e & 31);
                w0 = __shfl_sync(FULL, wv, e & 31);
                if (e < m) {
                    uint4 u0 = H4[(size_t)i0 * 16 + c];
                    acc8(acc, u0, w0);
                }
            }
        }
        done += m;
    }

#pragma unroll
    for (int k = 0; k < 8; k++)
        acc[k] += __shfl_xor_sync(FULL, acc[k], 16);

    float4 b0 = ((const float4*)b)[c * 2];
    float4 b1 = ((const float4*)b)[c * 2 + 1];
    float o[8];
    o[0] = tanhf(di * acc[0] + b0.x);
    o[1] = tanhf(di * acc[1] + b0.y);
    o[2] = tanhf(di * acc[2] + b0.z);
    o[3] = tanhf(di * acc[3] + b0.w);
    o[4] = tanhf(di * acc[4] + b1.x);
    o[5] = tanhf(di * acc[5] + b1.y);
    o[6] = tanhf(di * acc[6] + b1.z);
    o[7] = tanhf(di * acc[7] + b1.w);

    if (p == 0) {
        if (outh) {
            __half2 h0 = __floats2half2_rn(o[0], o[1]);
            __half2 h1 = __floats2half2_rn(o[2], o[3]);
            __half2 h2 = __floats2half2_rn(o[4], o[5]);
            __half2 h3 = __floats2half2_rn(o[6], o[7]);
            uint4 u;
            u.x = *(unsigned*)&h0; u.y = *(unsigned*)&h1;
            u.z = *(unsigned*)&h2; u.w = *(unsigned*)&h3;
            ((uint4*)outh)[(size_t)node * 16 + c] = u;
        } else {
            ((float4*)outf)[(size_t)node * 32 + c * 2] =
                make_float4(o[0], o[1], o[2], o[3]);
            ((float4*)outf)[(size_t)node * 32 + c * 2 + 1] =
                make_float4(o[4], o[5], o[6], o[7]);
        }
    }
    if (fcout) {
        float4 wA = ((const float4*)Wfc)[c * 2];
        float4 wB = ((const float4*)Wfc)[c * 2 + 1];
        float s = o[0] * wA.x + o[1] * wA.y + o[2] * wA.z + o[3] * wA.w +
                  o[4] * wB.x + o[5] * wB.y + o[6] * wB.z + o[7] * wB.w;
#pragma unroll
        for (int off = 8; off; off >>= 1)
            s += __shfl_xor_sync(FULL, s, off);
        if (lane == 0) fcout[node] = 1.0f / (1.0f + expf(-(s + bfc[0])));
    }
}

// ---------------- launch ----------------
extern "C" void kernel_launch(void* const* d_in, const int* in_sizes, int n_in,
                              void* d_out, int out_size) {
    const float* x   = (const float*)d_in[0];
    const int*   eb  = (const int*)d_in[1];
    const float* W1  = (const float*)d_in[2];
    const float* b1  = (const float*)d_in[3];
    const float* W2  = (const float*)d_in[4];
    const float* b2  = (const float*)d_in[5];
    const float* Wfc = (const float*)d_in[6];
    const float* bfc = (const float*)d_in[7];

    int n = in_sizes[0] / DD;
    int e = in_sizes[1] / 2;

    float* out = (float*)d_out;
    float* emb = out + n;

    __half *pa, *pf;
    int* pcnt;
    cudaGetSymbolAddress((void**)&pa, g_a16);
    cudaGetSymbolAddress((void**)&pf, g_f16);
    cudaGetSymbolAddress((void**)&pcnt, g_cnt);
    __nv_bfloat16 *w1h, *w1l, *w2h, *w2l;
    cudaGetSymbolAddress((void**)&w1h, g_wthi);
    cudaGetSymbolAddress((void**)&w1l, g_wtlo);
    w2h = w1h + DD * DD;
    w2l = w1l + DD * DD;

    static cudaStream_t s1 = nullptr;
    static cudaEvent_t evF = nullptr, evJ = nullptr;
    static int init_done = 0;
    const int gemm_smem = 4 * 128 * KP * 4;
    if (!init_done) {
        cudaFuncSetAttribute(k_gemm_tc,
                             cudaFuncAttributeMaxDynamicSharedMemorySize,
                             gemm_smem);
        cudaStreamCreateWithFlags(&s1, cudaStreamNonBlocking);
        cudaEventCreateWithFlags(&evF, cudaEventDisableTiming);
        cudaEventCreateWithFlags(&evJ, cudaEventDisableTiming);
        init_done = 1;
    }

    const int T = 256;
    int nb = (n + 1023) / 1024;
    int gblocks = (n + 127) / 128;
    int ablocks = (n * 32 + T - 1) / T;

    // --- fork: CSR preprocessing on s1, weight-conv + GEMM1 on default ---
    cudaEventRecord(evF, 0);
    cudaStreamWaitEvent(s1, evF, 0);

    cudaMemsetAsync(pcnt, 0, (size_t)n * sizeof(int), s1);
    k_detect<<<1, 256, 0, s1>>>(eb);
    k_hist<<<(e + T - 1) / T, T, 0, s1>>>(eb, e);
    k_scanA<<<nb, 1024, 0, s1>>>(n);
    k_scanB<<<1, 128, 0, s1>>>(nb);
    k_scanC<<<(n + T - 1) / T, T, 0, s1>>>(n);
    k_fill<<<(e + T - 1) / T, T, 0, s1>>>(eb, e);
    cudaEventRecord(evJ, s1);

    k_convW<<<128, 256>>>(W1, W2);
    k_gemm_tc<<<gblocks, 256, gemm_smem>>>(x, 0, w1h, w1l, pa, n);

    cudaStreamWaitEvent(0, evJ, 0);

    // --- layer 1 (fp16 activations) ---
    k_agg16<<<ablocks, T>>>(pa, b1, pf, nullptr, nullptr, nullptr, nullptr, n);
    // --- layer 2 + fused FC head ---
    k_gemm_tc<<<gblocks, 256, gemm_smem>>>(pf, 1, w2h, w2l, pa, n);
    k_agg16<<<ablocks, T>>>(pa, b2, nullptr, emb, Wfc, bfc, out, n);
}

// round 6
// speedup vs baseline: 1.6835x; 1.0592x over previous
#include <cuda_runtime.h>
#include <cuda_fp16.h>
#include <math.h>
#include <stdint.h>

#define NN 100000
#define EE 1600000
#define DD 128
#define KP 68   // padded smem row stride in 32-bit words (136 halves)
#define FULLM 0xFFFFFFFFu

// ---------------- device scratch (no allocations allowed) ----------------
__device__ int    g_rowptr[NN + 1];
__device__ int    g_cnt[NN];          // zero-init; re-zeroed by k_scanC each run
__device__ int    g_cursor[NN];
__device__ float  g_dinv[NN];
__device__ int2   g_cedge[EE];        // (src, dinv[src] bits), grouped by dst
__device__ int    g_bsums[128];
__device__ __half g_a16[(size_t)NN * DD];  // GEMM output (gather source)
__device__ __half g_f16[(size_t)NN * DD];  // layer-1 activations

// ---------------- inline edge-dtype detection (per warp) ----------------
__device__ __forceinline__ int detect64(const int* __restrict__ eb) {
    unsigned nz = 0;
#pragma unroll
    for (int i = (threadIdx.x & 31); i < 128; i += 32)
        nz |= (eb[2 * i + 1] != 0);
    return __ballot_sync(FULLM, nz) == 0;   // all-zero odd words -> int64
}

// ---------------- preprocessing ----------------
__global__ void k_hist(const int* __restrict__ eb, int e) {
    int is64 = detect64(eb);
    int i = blockIdx.x * blockDim.x + threadIdx.x;
    if (i >= e) return;
    int d = is64 ? eb[2 * (e + i)] : eb[e + i];
    atomicAdd(&g_cnt[d], 1);
}

__global__ void k_scanA(int n) {
    __shared__ int sh[1024];
    int gi = blockIdx.x * 1024 + threadIdx.x;
    int v = (gi < n) ? g_cnt[gi] : 0;
    sh[threadIdx.x] = v;
    __syncthreads();
    for (int off = 1; off < 1024; off <<= 1) {
        int x = sh[threadIdx.x];
        int y = (threadIdx.x >= off) ? sh[threadIdx.x - off] : 0;
        __syncthreads();
        sh[threadIdx.x] = x + y;
        __syncthreads();
    }
    int incl = sh[threadIdx.x];
    if (gi < n) g_rowptr[gi] = incl - v;   // block-local exclusive
    if (threadIdx.x == 1023) g_bsums[blockIdx.x] = incl;
}

// scanC: block-redundant scan of block sums + finalize rowptr/cursor/dinv,
// and reset g_cnt for the next graph replay.
__global__ void k_scanC(int n, int e) {
    __shared__ int sh[128];
    int t = threadIdx.x;
    int nb = (n + 1023) >> 10;
    if (t < 128) sh[t] = (t < nb) ? g_bsums[t] : 0;
    __syncthreads();
    for (int off = 1; off < 128; off <<= 1) {
        int x = 0, y = 0;
        if (t < 128) { x = sh[t]; y = (t >= off) ? sh[t - off] : 0; }
        __syncthreads();
        if (t < 128) sh[t] = x + y;
        __syncthreads();
    }
    int i = blockIdx.x * blockDim.x + t;
    if (i < n) {
        int blk = i >> 10;
        int ex = blk ? sh[blk - 1] : 0;
        int rp = g_rowptr[i] + ex;
        g_rowptr[i] = rp;
        g_cursor[i] = rp;
        g_dinv[i] = rsqrtf((float)(g_cnt[i] + 1));
        g_cnt[i] = 0;                      // replay-safe reset
    }
    if (blockIdx.x == 0 && t == 0) g_rowptr[n] = e;
}

__global__ void k_fill(const int* __restrict__ eb, int e) {
    int is64 = detect64(eb);
    int i = blockIdx.x * blockDim.x + threadIdx.x;
    if (i >= e) return;
    int s, d;
    if (is64) { s = eb[2 * i]; d = eb[2 * (e + i)]; }
    else      { s = eb[i];     d = eb[e + i]; }
    int p = atomicAdd(&g_cursor[d], 1);
    g_cedge[p] = make_int2(s, __float_as_int(g_dinv[s]));
}

// ---------------- tensor-core GEMM (mma.sync fp16 hi/lo) ----------------
// C[n x 128] = A[n x 128] @ W[128 x 128], W converted in-prologue.
// mode 0: A fp32 -> 3 passes (ah*bh + ah*bl + al*bh)
// mode 1: A fp16 (exact) -> 2 passes (ah*bh + ah*bl)
__device__ __forceinline__ void mma_f16(float* d, const unsigned* a,
                                        unsigned b0, unsigned b1) {
    asm volatile(
        "mma.sync.aligned.m16n8k16.row.col.f32.f16.f16.f32 "
        "{%0,%1,%2,%3}, {%4,%5,%6,%7}, {%8,%9}, {%0,%1,%2,%3};\n"
        : "+f"(d[0]), "+f"(d[1]), "+f"(d[2]), "+f"(d[3])
        : "r"(a[0]), "r"(a[1]), "r"(a[2]), "r"(a[3]), "r"(b0), "r"(b1));
}

__global__ void __launch_bounds__(256) k_gemm_tc(
    const void* __restrict__ Ain, int mode,
    const float* __restrict__ W,
    __half* __restrict__ C, int n) {
    extern __shared__ unsigned smu[];
    unsigned* Ahi = smu;
    unsigned* Alo = Ahi + 128 * KP;
    unsigned* Bhi = Alo + 128 * KP;
    unsigned* Blo = Bhi + 128 * KP;
    const int tid = threadIdx.x;
    const int row0 = blockIdx.x * 128;

    // ---- W[k][n] fp32 -> W^T[n][k] fp16 hi/lo into padded smem ----
    for (int i = tid; i < 8192; i += 256) {
        int nn_ = i & 127;          // output column (consecutive across threads)
        int kp = i >> 7;            // k pair index 0..63
        int k = kp * 2;
        float w0 = W[k * DD + nn_];
        float w1 = W[(k + 1) * DD + nn_];
        __half h0 = __float2half_rn(w0), h1 = __float2half_rn(w1);
        __half2 hi = __halves2half2(h0, h1);
        __half2 lo = __floats2half2_rn(w0 - __half2float(h0),
                                       w1 - __half2float(h1));
        Bhi[nn_ * KP + kp] = *(unsigned*)&hi;
        Blo[nn_ * KP + kp] = *(unsigned*)&lo;
    }

    // ---- A tile ----
    if (mode == 0) {
        const float4* A4 = (const float4*)Ain;
        for (int i = tid; i < 4096; i += 256) {
            int r = i >> 5, j = i & 31;
            float4 v = make_float4(0.f, 0.f, 0.f, 0.f);
            if (row0 + r < n) v = A4[(size_t)(row0 + r) * 32 + j];
            __half2 h01 = __floats2half2_rn(v.x, v.y);
            __half2 h23 = __floats2half2_rn(v.z, v.w);
            float2 f01 = __half22float2(h01);
            float2 f23 = __half22float2(h23);
            __half2 l01 = __floats2half2_rn(v.x - f01.x, v.y - f01.y);
            __half2 l23 = __floats2half2_rn(v.z - f23.x, v.w - f23.y);
            *(uint2*)(Ahi + r * KP + 2 * j) =
                make_uint2(*(unsigned*)&h01, *(unsigned*)&h23);
            *(uint2*)(Alo + r * KP + 2 * j) =
                make_uint2(*(unsigned*)&l01, *(unsigned*)&l23);
        }
    } else {
        const uint4* A4 = (const uint4*)Ain;   // fp16 rows: 16 uint4 per row
        for (int i = tid; i < 2048; i += 256) {
            int r = i >> 4, j = i & 15;
            uint4 u = make_uint4(0, 0, 0, 0);
            if (row0 + r < n) u = A4[(size_t)(row0 + r) * 16 + j];
            *(uint4*)(Ahi + r * KP + 4 * j) = u;   // r*KP words = 272B, 16B-aligned
        }
    }
    __syncthreads();

    const int wid = tid >> 5, lane = tid & 31;
    const int grp = lane >> 2, tig = lane & 3;
    const int mrow0 = (wid >> 1) * 32;
    const int ncol0 = (wid & 1) * 64;

    float acc[2][8][4];
#pragma unroll
    for (int mi = 0; mi < 2; mi++)
#pragma unroll
        for (int ni = 0; ni < 8; ni++)
#pragma unroll
            for (int q = 0; q < 4; q++) acc[mi][ni][q] = 0.f;

#pragma unroll
    for (int ks = 0; ks < 8; ks++) {
        const int kw = ks * 8 + tig;
        unsigned ah[2][4], al[2][4];
#pragma unroll
        for (int mi = 0; mi < 2; mi++) {
            int r0 = mrow0 + mi * 16 + grp;
            ah[mi][0] = Ahi[r0 * KP + kw];
            ah[mi][1] = Ahi[(r0 + 8) * KP + kw];
            ah[mi][2] = Ahi[r0 * KP + kw + 4];
            ah[mi][3] = Ahi[(r0 + 8) * KP + kw + 4];
            if (mode == 0) {
                al[mi][0] = Alo[r0 * KP + kw];
                al[mi][1] = Alo[(r0 + 8) * KP + kw];
                al[mi][2] = Alo[r0 * KP + kw + 4];
                al[mi][3] = Alo[(r0 + 8) * KP + kw + 4];
            }
        }
#pragma unroll
        for (int ni = 0; ni < 8; ni++) {
            int nr = ncol0 + ni * 8 + grp;
            unsigned bh0 = Bhi[nr * KP + kw], bh1 = Bhi[nr * KP + kw + 4];
            unsigned bl0 = Blo[nr * KP + kw], bl1 = Blo[nr * KP + kw + 4];
#pragma unroll
            for (int mi = 0; mi < 2; mi++) {
                mma_f16(acc[mi][ni], ah[mi], bh0, bh1);
                mma_f16(acc[mi][ni], ah[mi], bl0, bl1);
                if (mode == 0)
                    mma_f16(acc[mi][ni], al[mi], bh0, bh1);
            }
        }
    }

#pragma unroll
    for (int mi = 0; mi < 2; mi++) {
        int r = row0 + mrow0 + mi * 16 + grp;
#pragma unroll
        for (int ni = 0; ni < 8; ni++) {
            int c = ncol0 + ni * 8 + tig * 2;
            if (r < n)
                *(__half2*)(C + (size_t)r * DD + c) =
                    __floats2half2_rn(acc[mi][ni][0], acc[mi][ni][1]);
            if (r + 8 < n)
                *(__half2*)(C + (size_t)(r + 8) * DD + c) =
                    __floats2half2_rn(acc[mi][ni][2], acc[mi][ni][3]);
        }
    }
}

// ---------------- aggregation (one warp per node, 2 edge-slots) ----------
__device__ __forceinline__ void acc8(float* a, uint4 u, float w) {
    float2 f;
    f = __half22float2(*(__half2*)&u.x); a[0] += w * f.x; a[1] += w * f.y;
    f = __half22float2(*(__half2*)&u.y); a[2] += w * f.x; a[3] += w * f.y;
    f = __half22float2(*(__half2*)&u.z); a[4] += w * f.x; a[5] += w * f.y;
    f = __half22float2(*(__half2*)&u.w); a[6] += w * f.x; a[7] += w * f.y;
}

__global__ void __launch_bounds__(256) k_agg16(
    const __half* __restrict__ H, const float* __restrict__ b,
    __half* __restrict__ outh, float* __restrict__ outf,
    const float* __restrict__ Wfc, const float* __restrict__ bfc,
    float* __restrict__ fcout, int n) {
    int node = (blockIdx.x * blockDim.x + threadIdx.x) >> 5;
    int lane = threadIdx.x & 31;
    if (node >= n) return;
    int p = lane >> 4, c = lane & 15;
    const uint4* H4 = (const uint4*)H;
    float di = g_dinv[node];

    float acc[8];
    {
        uint4 u = H4[(size_t)node * 16 + c];
        float w = (p == 0) ? di : 0.f;
        float2 f;
        f = __half22float2(*(__half2*)&u.x); acc[0] = w * f.x; acc[1] = w * f.y;
        f = __half22float2(*(__half2*)&u.y); acc[2] = w * f.x; acc[3] = w * f.y;
        f = __half22float2(*(__half2*)&u.z); acc[4] = w * f.x; acc[5] = w * f.y;
        f = __half22float2(*(__half2*)&u.w); acc[6] = w * f.x; acc[7] = w * f.y;
    }

    int beg = g_rowptr[node];
    int cnt = g_rowptr[node + 1] - beg;
    int done = 0;
    while (done < cnt) {
        int m = cnt - done;
        if (m > 32) m = 32;
        int idx = 0;
        float wv = 0.f;
        if (lane < m) {
            int2 ew = g_cedge[beg + done + lane];
            idx = ew.x;
            wv = __int_as_float(ew.y);
        }
        int j = 0;
        for (; j + 4 <= m; j += 4) {
            int e0 = j + p, e1 = j + 2 + p;
            int i0 = __shfl_sync(FULLM, idx, e0);
            float w0 = __shfl_sync(FULLM, wv, e0);
            int i1 = __shfl_sync(FULLM, idx, e1);
            float w1 = __shfl_sync(FULLM, wv, e1);
            uint4 u0 = H4[(size_t)i0 * 16 + c];
            uint4 u1 = H4[(size_t)i1 * 16 + c];
            acc8(acc, u0, w0);
            acc8(acc, u1, w1);
        }
        if (j < m) {
            int e = j + p;
            int i0 = __shfl_sync(FULLM, idx, e & 31);
            float w0 = __shfl_sync(FULLM, wv, e & 31);
            if (e < m) {
                uint4 u0 = H4[(size_t)i0 * 16 + c];
                acc8(acc, u0, w0);
            }
            j += 2;
            if (j < m) {
                e = j + p;
                i0 = __shfl_sync(FULLM, idx, e & 31);
                w0 = __shfl_sync(FULLM, wv, e & 31);
                if (e < m) {
                    uint4 u0 = H4[(size_t)i0 * 16 + c];
                    acc8(acc, u0, w0);
                }
            }
        }
        done += m;
    }

#pragma unroll
    for (int k = 0; k < 8; k++)
        acc[k] += __shfl_xor_sync(FULLM, acc[k], 16);

    float4 b0 = ((const float4*)b)[c * 2];
    float4 b1 = ((const float4*)b)[c * 2 + 1];
    float o[8];
    o[0] = tanhf(di * acc[0] + b0.x);
    o[1] = tanhf(di * acc[1] + b0.y);
    o[2] = tanhf(di * acc[2] + b0.z);
    o[3] = tanhf(di * acc[3] + b0.w);
    o[4] = tanhf(di * acc[4] + b1.x);
    o[5] = tanhf(di * acc[5] + b1.y);
    o[6] = tanhf(di * acc[6] + b1.z);
    o[7] = tanhf(di * acc[7] + b1.w);

    if (p == 0) {
        if (outh) {
            __half2 h0 = __floats2half2_rn(o[0], o[1]);
            __half2 h1 = __floats2half2_rn(o[2], o[3]);
            __half2 h2 = __floats2half2_rn(o[4], o[5]);
            __half2 h3 = __floats2half2_rn(o[6], o[7]);
            uint4 u;
            u.x = *(unsigned*)&h0; u.y = *(unsigned*)&h1;
            u.z = *(unsigned*)&h2; u.w = *(unsigned*)&h3;
            ((uint4*)outh)[(size_t)node * 16 + c] = u;
        } else {
            ((float4*)outf)[(size_t)node * 32 + c * 2] =
                make_float4(o[0], o[1], o[2], o[3]);
            ((float4*)outf)[(size_t)node * 32 + c * 2 + 1] =
                make_float4(o[4], o[5], o[6], o[7]);
        }
    }
    if (fcout) {
        float4 wA = ((const float4*)Wfc)[c * 2];
        float4 wB = ((const float4*)Wfc)[c * 2 + 1];
        float s = o[0] * wA.x + o[1] * wA.y + o[2] * wA.z + o[3] * wA.w +
                  o[4] * wB.x + o[5] * wB.y + o[6] * wB.z + o[7] * wB.w;
#pragma unroll
        for (int off = 8; off; off >>= 1)
            s += __shfl_xor_sync(FULLM, s, off);
        if (lane == 0) fcout[node] = 1.0f / (1.0f + expf(-(s + bfc[0])));
    }
}

// ---------------- launch ----------------
extern "C" void kernel_launch(void* const* d_in, const int* in_sizes, int n_in,
                              void* d_out, int out_size) {
    const float* x   = (const float*)d_in[0];
    const int*   eb  = (const int*)d_in[1];
    const float* W1  = (const float*)d_in[2];
    const float* b1  = (const float*)d_in[3];
    const float* W2  = (const float*)d_in[4];
    const float* b2  = (const float*)d_in[5];
    const float* Wfc = (const float*)d_in[6];
    const float* bfc = (const float*)d_in[7];

    int n = in_sizes[0] / DD;
    int e = in_sizes[1] / 2;

    float* out = (float*)d_out;
    float* emb = out + n;

    __half *pa, *pf;
    cudaGetSymbolAddress((void**)&pa, g_a16);
    cudaGetSymbolAddress((void**)&pf, g_f16);

    static cudaStream_t s1 = nullptr;
    static cudaEvent_t evF = nullptr, evJ = nullptr;
    static int init_done = 0;
    const int gemm_smem = 4 * 128 * KP * 4;   // 139,264 B
    if (!init_done) {
        cudaFuncSetAttribute(k_gemm_tc,
                             cudaFuncAttributeMaxDynamicSharedMemorySize,
                             gemm_smem);
        cudaStreamCreateWithFlags(&s1, cudaStreamNonBlocking);
        cudaEventCreateWithFlags(&evF, cudaEventDisableTiming);
        cudaEventCreateWithFlags(&evJ, cudaEventDisableTiming);
        init_done = 1;
    }

    const int T = 256;
    int nb = (n + 1023) / 1024;
    int gblocks = (n + 127) / 128;
    int ablocks = (n * 32 + T - 1) / T;

    // fork: GEMM1 on default stream, CSR preprocessing on s1
    cudaEventRecord(evF, 0);
    cudaStreamWaitEvent(s1, evF, 0);

    k_gemm_tc<<<gblocks, 256, gemm_smem>>>(x, 0, W1, pa, n);        // launch 1

    k_hist<<<(e + T - 1) / T, T, 0, s1>>>(eb, e);                   // 2
    k_scanA<<<nb, 1024, 0, s1>>>(n);                                // 3
    k_scanC<<<(n + T - 1) / T, T, 0, s1>>>(n, e);                   // 4
    k_fill<<<(e + T - 1) / T, T, 0, s1>>>(eb, e);                   // 5
    cudaEventRecord(evJ, s1);
    cudaStreamWaitEvent(0, evJ, 0);

    // layer 1 (agg is launch 6 -> visible to ncu -s 5 -c 1)
    k_agg16<<<ablocks, T>>>(pa, b1, pf, nullptr, nullptr, nullptr, nullptr, n);
    // layer 2 (A fp16 -> 2-pass GEMM) + fused FC head
    k_gemm_tc<<<gblocks, 256, gemm_smem>>>(pf, 1, W2, pa, n);
    k_agg16<<<ablocks, T>>>(pa, b2, nullptr, emb, Wfc, bfc, out, n);
}

// round 7
// speedup vs baseline: 1.9099x; 1.1344x over previous
#include <cuda_runtime.h>
#include <cuda_fp16.h>
#include <math.h>
#include <stdint.h>

#define NN 100000
#define EE 1600000
#define DD 128
#define KP 68          // padded smem row stride in 32-bit words
#define NCH 4          // pipeline chunks
#define FULLM 0xFFFFFFFFu

// ---------------- device scratch (no allocations allowed) ----------------
__device__ int    g_rowptr[NN + 1];
__device__ int    g_cnt[NN];          // zero-init; re-zeroed by k_scanC
__device__ int    g_cursor[NN];
__device__ float  g_dinv[NN];
__device__ int2   g_cedge[EE];        // (src, dinv[src] bits), grouped by dst
__device__ int    g_bsums[128];
__device__ __half g_x16[(size_t)NN * DD];  // fp16 copy of input x
__device__ __half g_ax[(size_t)NN * DD];   // aggregated rows (both layers)
__device__ __half g_f16[(size_t)NN * DD];  // layer-1 activations f

// ---------------- x -> fp16 ----------------
__global__ void k_cvt(const float* __restrict__ x, int total8) {
    int i = blockIdx.x * blockDim.x + threadIdx.x;
    if (i >= total8) return;
    const float4* x4 = (const float4*)x;
    float4 a = x4[i * 2], b = x4[i * 2 + 1];
    __half2 h0 = __floats2half2_rn(a.x, a.y);
    __half2 h1 = __floats2half2_rn(a.z, a.w);
    __half2 h2 = __floats2half2_rn(b.x, b.y);
    __half2 h3 = __floats2half2_rn(b.z, b.w);
    uint4 u;
    u.x = *(unsigned*)&h0; u.y = *(unsigned*)&h1;
    u.z = *(unsigned*)&h2; u.w = *(unsigned*)&h3;
    ((uint4*)g_x16)[i] = u;
}

// ---------------- edge dtype detection (per warp) ----------------
__device__ __forceinline__ int detect64(const int* __restrict__ eb) {
    unsigned nz = 0;
#pragma unroll
    for (int i = (threadIdx.x & 31); i < 128; i += 32)
        nz |= (eb[2 * i + 1] != 0);
    return __ballot_sync(FULLM, nz) == 0;
}

// ---------------- preprocessing ----------------
__global__ void k_hist(const int* __restrict__ eb, int e) {
    int is64 = detect64(eb);
    int i = blockIdx.x * blockDim.x + threadIdx.x;
    if (i >= e) return;
    int d = is64 ? eb[2 * (e + i)] : eb[e + i];
    atomicAdd(&g_cnt[d], 1);
}

__global__ void k_scanA(int n) {
    __shared__ int sh[1024];
    int gi = blockIdx.x * 1024 + threadIdx.x;
    int v = (gi < n) ? g_cnt[gi] : 0;
    sh[threadIdx.x] = v;
    __syncthreads();
    for (int off = 1; off < 1024; off <<= 1) {
        int x = sh[threadIdx.x];
        int y = (threadIdx.x >= off) ? sh[threadIdx.x - off] : 0;
        __syncthreads();
        sh[threadIdx.x] = x + y;
        __syncthreads();
    }
    int incl = sh[threadIdx.x];
    if (gi < n) g_rowptr[gi] = incl - v;
    if (threadIdx.x == 1023) g_bsums[blockIdx.x] = incl;
}

__global__ void k_scanC(int n, int e) {
    __shared__ int sh[128];
    int t = threadIdx.x;
    int nb = (n + 1023) >> 10;
    if (t < 128) sh[t] = (t < nb) ? g_bsums[t] : 0;
    __syncthreads();
    for (int off = 1; off < 128; off <<= 1) {
        int x = 0, y = 0;
        if (t < 128) { x = sh[t]; y = (t >= off) ? sh[t - off] : 0; }
        __syncthreads();
        if (t < 128) sh[t] = x + y;
        __syncthreads();
    }
    int i = blockIdx.x * blockDim.x + t;
    if (i < n) {
        int blk = i >> 10;
        int ex = blk ? sh[blk - 1] : 0;
        int rp = g_rowptr[i] + ex;
        g_rowptr[i] = rp;
        g_cursor[i] = rp;
        g_dinv[i] = rsqrtf((float)(g_cnt[i] + 1));
        g_cnt[i] = 0;
    }
    if (blockIdx.x == 0 && t == 0) g_rowptr[n] = e;
}

__global__ void k_fill(const int* __restrict__ eb, int e) {
    int is64 = detect64(eb);
    int i = blockIdx.x * blockDim.x + threadIdx.x;
    if (i >= e) return;
    int s, d;
    if (is64) { s = eb[2 * i]; d = eb[2 * (e + i)]; }
    else      { s = eb[i];     d = eb[e + i]; }
    int p = atomicAdd(&g_cursor[d], 1);
    g_cedge[p] = make_int2(s, __float_as_int(g_dinv[s]));
}

// ---------------- aggregation: O[d] = dinv[d]*(sum_s dinv[s]*X[s] + dinv[d]*X[d])
// One warp per node, 2 edge-slots of 16 lanes, 4 row-gathers in flight.
__device__ __forceinline__ void acc8(float* a, uint4 u, float w) {
    float2 f;
    f = __half22float2(*(__half2*)&u.x); a[0] += w * f.x; a[1] += w * f.y;
    f = __half22float2(*(__half2*)&u.y); a[2] += w * f.x; a[3] += w * f.y;
    f = __half22float2(*(__half2*)&u.z); a[4] += w * f.x; a[5] += w * f.y;
    f = __half22float2(*(__half2*)&u.w); a[6] += w * f.x; a[7] += w * f.y;
}

__global__ void __launch_bounds__(256) k_agg(const __half* __restrict__ X,
                                             __half* __restrict__ O,
                                             int n0, int n1) {
    int node = n0 + ((blockIdx.x * blockDim.x + threadIdx.x) >> 5);
    int lane = threadIdx.x & 31;
    if (node >= n1) return;
    int p = lane >> 4, c = lane & 15;
    const uint4* X4 = (const uint4*)X;
    float di = g_dinv[node];

    float acc[8];
    {
        uint4 u = X4[(size_t)node * 16 + c];
        float w = (p == 0) ? di : 0.f;
        float2 f;
        f = __half22float2(*(__half2*)&u.x); acc[0] = w * f.x; acc[1] = w * f.y;
        f = __half22float2(*(__half2*)&u.y); acc[2] = w * f.x; acc[3] = w * f.y;
        f = __half22float2(*(__half2*)&u.z); acc[4] = w * f.x; acc[5] = w * f.y;
        f = __half22float2(*(__half2*)&u.w); acc[6] = w * f.x; acc[7] = w * f.y;
    }

    int beg = g_rowptr[node];
    int cnt = g_rowptr[node + 1] - beg;
    int done = 0;
    while (done < cnt) {
        int m = cnt - done;
        if (m > 32) m = 32;
        int idx = 0;
        float wv = 0.f;
        if (lane < m) {
            int2 ew = g_cedge[beg + done + lane];
            idx = ew.x;
            wv = __int_as_float(ew.y);
        }
        int j = 0;
        for (; j + 8 <= m; j += 8) {
            int i0 = __shfl_sync(FULLM, idx, j + p);
            float w0 = __shfl_sync(FULLM, wv, j + p);
            int i1 = __shfl_sync(FULLM, idx, j + 2 + p);
            float w1 = __shfl_sync(FULLM, wv, j + 2 + p);
            int i2 = __shfl_sync(FULLM, idx, j + 4 + p);
            float w2 = __shfl_sync(FULLM, wv, j + 4 + p);
            int i3 = __shfl_sync(FULLM, idx, j + 6 + p);
            float w3 = __shfl_sync(FULLM, wv, j + 6 + p);
            uint4 u0 = X4[(size_t)i0 * 16 + c];
            uint4 u1 = X4[(size_t)i1 * 16 + c];
            uint4 u2 = X4[(size_t)i2 * 16 + c];
            uint4 u3 = X4[(size_t)i3 * 16 + c];
            acc8(acc, u0, w0);
            acc8(acc, u1, w1);
            acc8(acc, u2, w2);
            acc8(acc, u3, w3);
        }
        for (; j + 2 <= m; j += 2) {
            int i0 = __shfl_sync(FULLM, idx, j + p);
            float w0 = __shfl_sync(FULLM, wv, j + p);
            uint4 u0 = X4[(size_t)i0 * 16 + c];
            acc8(acc, u0, w0);
        }
        if (j < m) {
            int i0 = __shfl_sync(FULLM, idx, j);
            float w0 = __shfl_sync(FULLM, wv, j);
            if (p == 0) {
                uint4 u0 = X4[(size_t)i0 * 16 + c];
                acc8(acc, u0, w0);
            }
        }
        done += m;
    }

#pragma unroll
    for (int k = 0; k < 8; k++)
        acc[k] += __shfl_xor_sync(FULLM, acc[k], 16);

    if (p == 0) {
        __half2 h0 = __floats2half2_rn(di * acc[0], di * acc[1]);
        __half2 h1 = __floats2half2_rn(di * acc[2], di * acc[3]);
        __half2 h2 = __floats2half2_rn(di * acc[4], di * acc[5]);
        __half2 h3 = __floats2half2_rn(di * acc[6], di * acc[7]);
        uint4 u;
        u.x = *(unsigned*)&h0; u.y = *(unsigned*)&h1;
        u.z = *(unsigned*)&h2; u.w = *(unsigned*)&h3;
        ((uint4*)O)[(size_t)node * 16 + c] = u;
    }
}

// ---------------- GEMM + fused activation epilogue ----------------
// C[r] = A[r] @ W (A fp16 exact, W fp16 hi/lo 2-pass), then
//  mode 0: f = tanh(C + b) -> fp16 outh
//  mode 1: emb = tanh(C + b) -> fp32 outf; fc = sigmoid(emb . Wfc + bfc) -> fcout
__device__ __forceinline__ void mma_f16(float* d, const unsigned* a,
                                        unsigned b0, unsigned b1) {
    asm volatile(
        "mma.sync.aligned.m16n8k16.row.col.f32.f16.f16.f32 "
        "{%0,%1,%2,%3}, {%4,%5,%6,%7}, {%8,%9}, {%0,%1,%2,%3};\n"
        : "+f"(d[0]), "+f"(d[1]), "+f"(d[2]), "+f"(d[3])
        : "r"(a[0]), "r"(a[1]), "r"(a[2]), "r"(a[3]), "r"(b0), "r"(b1));
}

__global__ void __launch_bounds__(256) k_gemm(
    const __half* __restrict__ A, const float* __restrict__ W,
    const float* __restrict__ bias,
    __half* __restrict__ outh,                    // mode 0
    float* __restrict__ outf,                     // mode 1: emb
    const float* __restrict__ Wfc, const float* __restrict__ bfc,
    float* __restrict__ fcout,                    // mode 1: fc head
    int n0, int n, int mode) {
    extern __shared__ unsigned smu[];
    unsigned* Ahi = smu;
    unsigned* Bhi = Ahi + 128 * KP;
    unsigned* Blo = Bhi + 128 * KP;
    float* sfc = (float*)(Blo + 128 * KP);   // 128
    float* sWf = sfc + 128;                  // 128
    float* sB  = sWf + 128;                  // 128
    const int tid = threadIdx.x;
    const int row0 = n0 + blockIdx.x * 128;

    // W[k][n] fp32 -> W^T[n][k] fp16 hi/lo
    for (int i = tid; i < 8192; i += 256) {
        int nn_ = i & 127;
        int kp = i >> 7;
        int k = kp * 2;
        float w0 = W[k * DD + nn_];
        float w1 = W[(k + 1) * DD + nn_];
        __half h0 = __float2half_rn(w0), h1 = __float2half_rn(w1);
        __half2 hi = __halves2half2(h0, h1);
        __half2 lo = __floats2half2_rn(w0 - __half2float(h0),
                                       w1 - __half2float(h1));
        Bhi[nn_ * KP + kp] = *(unsigned*)&hi;
        Blo[nn_ * KP + kp] = *(unsigned*)&lo;
    }
    // A rows (fp16, exact copy)
    {
        const uint4* A4 = (const uint4*)A;
        for (int i = tid; i < 2048; i += 256) {
            int r = i >> 4, j = i & 15;
            uint4 u = make_uint4(0, 0, 0, 0);
            if (row0 + r < n) u = A4[(size_t)(row0 + r) * 16 + j];
            *(uint4*)(Ahi + r * KP + 4 * j) = u;
        }
    }
    if (tid < 128) {
        sB[tid] = bias[tid];
        sfc[tid] = 0.f;
        if (mode == 1) sWf[tid] = Wfc[tid];
    }
    __syncthreads();

    const int wid = tid >> 5, lane = tid & 31;
    const int grp = lane >> 2, tig = lane & 3;
    const int mrow0 = (wid >> 1) * 32;
    const int ncol0 = (wid & 1) * 64;

    float acc[2][8][4];
#pragma unroll
    for (int mi = 0; mi < 2; mi++)
#pragma unroll
        for (int ni = 0; ni < 8; ni++)
#pragma unroll
            for (int q = 0; q < 4; q++) acc[mi][ni][q] = 0.f;

#pragma unroll
    for (int ks = 0; ks < 8; ks++) {
        const int kw = ks * 8 + tig;
        unsigned ah[2][4];
#pragma unroll
        for (int mi = 0; mi < 2; mi++) {
            int r0 = mrow0 + mi * 16 + grp;
            ah[mi][0] = Ahi[r0 * KP + kw];
            ah[mi][1] = Ahi[(r0 + 8) * KP + kw];
            ah[mi][2] = Ahi[r0 * KP + kw + 4];
            ah[mi][3] = Ahi[(r0 + 8) * KP + kw + 4];
        }
#pragma unroll
        for (int ni = 0; ni < 8; ni++) {
            int nr = ncol0 + ni * 8 + grp;
            unsigned bh0 = Bhi[nr * KP + kw], bh1 = Bhi[nr * KP + kw + 4];
            unsigned bl0 = Blo[nr * KP + kw], bl1 = Blo[nr * KP + kw + 4];
#pragma unroll
            for (int mi = 0; mi < 2; mi++) {
                mma_f16(acc[mi][ni], ah[mi], bh0, bh1);
                mma_f16(acc[mi][ni], ah[mi], bl0, bl1);
            }
        }
    }

    // ---- epilogue ----
#pragma unroll
    for (int mi = 0; mi < 2; mi++) {
        int rA = row0 + mrow0 + mi * 16 + grp;   // rows rA, rA+8
        float pA = 0.f, pB = 0.f;
#pragma unroll
        for (int ni = 0; ni < 8; ni++) {
            int ccol = ncol0 + ni * 8 + tig * 2;
            float bb0 = sB[ccol], bb1 = sB[ccol + 1];
            float v0 = tanhf(acc[mi][ni][0] + bb0);
            float v1 = tanhf(acc[mi][ni][1] + bb1);
            float v2 = tanhf(acc[mi][ni][2] + bb0);
            float v3 = tanhf(acc[mi][ni][3] + bb1);
            if (mode == 0) {
                if (rA < n)
                    *(__half2*)(outh + (size_t)rA * DD + ccol) =
                        __floats2half2_rn(v0, v1);
                if (rA + 8 < n)
                    *(__half2*)(outh + (size_t)(rA + 8) * DD + ccol) =
                        __floats2half2_rn(v2, v3);
            } else {
                if (rA < n)
                    *(float2*)(outf + (size_t)rA * DD + ccol) =
                        make_float2(v0, v1);
                if (rA + 8 < n)
                    *(float2*)(outf + (size_t)(rA + 8) * DD + ccol) =
                        make_float2(v2, v3);
                float wf0 = sWf[ccol], wf1 = sWf[ccol + 1];
                pA += v0 * wf0 + v1 * wf1;
                pB += v2 * wf0 + v3 * wf1;
            }
        }
        if (mode == 1) {
            int rl = mrow0 + mi * 16 + grp;
            if (rA < n) atomicAdd(&sfc[rl], pA);
            if (rA + 8 < n) atomicAdd(&sfc[rl + 8], pB);
        }
    }
    if (mode == 1) {
        __syncthreads();
        if (tid < 128) {
            int r = row0 + tid;
            if (r < n)
                fcout[r] = 1.0f / (1.0f + expf(-(sfc[tid] + bfc[0])));
        }
    }
}

// ---------------- launch ----------------
extern "C" void kernel_launch(void* const* d_in, const int* in_sizes, int n_in,
                              void* d_out, int out_size) {
    const float* x   = (const float*)d_in[0];
    const int*   eb  = (const int*)d_in[1];
    const float* W1  = (const float*)d_in[2];
    const float* b1  = (const float*)d_in[3];
    const float* W2  = (const float*)d_in[4];
    const float* b2  = (const float*)d_in[5];
    const float* Wfc = (const float*)d_in[6];
    const float* bfc = (const float*)d_in[7];

    int n = in_sizes[0] / DD;
    int e = in_sizes[1] / 2;

    float* out = (float*)d_out;
    float* emb = out + n;

    __half *px, *pa, *pf;
    cudaGetSymbolAddress((void**)&px, g_x16);
    cudaGetSymbolAddress((void**)&pa, g_ax);
    cudaGetSymbolAddress((void**)&pf, g_f16);

    static cudaStream_t s1 = nullptr, s2 = nullptr;
    static cudaEvent_t evF = nullptr, evP = nullptr, evG1 = nullptr,
                       evL = nullptr, evA[NCH], evB[NCH];
    static int init_done = 0;
    const int gemm_smem = (3 * 128 * KP + 384) * 4;   // 105,984 B
    if (!init_done) {
        cudaFuncSetAttribute(k_gemm,
                             cudaFuncAttributeMaxDynamicSharedMemorySize,
                             gemm_smem);
        cudaStreamCreateWithFlags(&s1, cudaStreamNonBlocking);
        cudaStreamCreateWithFlags(&s2, cudaStreamNonBlocking);
        cudaEventCreateWithFlags(&evF, cudaEventDisableTiming);
        cudaEventCreateWithFlags(&evP, cudaEventDisableTiming);
        cudaEventCreateWithFlags(&evG1, cudaEventDisableTiming);
        cudaEventCreateWithFlags(&evL, cudaEventDisableTiming);
        for (int c = 0; c < NCH; c++) {
            cudaEventCreateWithFlags(&evA[c], cudaEventDisableTiming);
            cudaEventCreateWithFlags(&evB[c], cudaEventDisableTiming);
        }
        init_done = 1;
    }

    const int T = 256;
    int nb = (n + 1023) / 1024;
    int chunk = (((n + NCH - 1) / NCH) + 127) & ~127;

    // fork preprocessing onto s1
    cudaEventRecord(evF, 0);
    cudaStreamWaitEvent(s1, evF, 0);
    k_hist<<<(e + T - 1) / T, T, 0, s1>>>(eb, e);
    k_scanA<<<nb, 1024, 0, s1>>>(n);
    k_scanC<<<(n + T - 1) / T, T, 0, s1>>>(n, e);
    k_fill<<<(e + T - 1) / T, T, 0, s1>>>(eb, e);
    cudaEventRecord(evP, s1);

    // x -> fp16 (overlaps preprocessing)
    k_cvt<<<(n * 16 + T - 1) / T, T>>>(x, n * 16);

    cudaStreamWaitEvent(0, evP, 0);

    // ---- layer 1: agg(x16) chunks pipelined with gemm1 ----
    for (int c = 0; c < NCH; c++) {
        int c0 = c * chunk, c1 = min(n, c0 + chunk);
        if (c0 >= n) break;
        int nodes = c1 - c0;
        k_agg<<<(nodes * 32 + T - 1) / T, T>>>(px, pa, c0, c1);
        cudaEventRecord(evA[c], 0);
        cudaStreamWaitEvent(s2, evA[c], 0);
        k_gemm<<<(nodes + 127) / 128, 256, gemm_smem, s2>>>(
            pa, W1, b1, pf, nullptr, nullptr, nullptr, nullptr, c0, n, 0);
    }
    cudaEventRecord(evG1, s2);
    cudaStreamWaitEvent(0, evG1, 0);

    // ---- layer 2: agg(f) chunks pipelined with gemm2 (+emb, +fc head) ----
    for (int c = 0; c < NCH; c++) {
        int c0 = c * chunk, c1 = min(n, c0 + chunk);
        if (c0 >= n) break;
        int nodes = c1 - c0;
        k_agg<<<(nodes * 32 + T - 1) / T, T>>>(pf, pa, c0, c1);
        cudaEventRecord(evB[c], 0);
        cudaStreamWaitEvent(s2, evB[c], 0);
        k_gemm<<<(nodes + 127) / 128, 256, gemm_smem, s2>>>(
            pa, W2, b2, nullptr, emb, Wfc, bfc, out, c0, n, 1);
    }
    cudaEventRecord(evL, s2);
    cudaStreamWaitEvent(0, evL, 0);
}